// round 13
// baseline (speedup 1.0000x reference)
#include <cuda_runtime.h>
#include <cuda_fp16.h>
#include <math.h>
#include <stdint.h>

// ---------------------------------------------------------------------------
// B=4, C=256, C16=16, H=W=64, N=4096. Attention: 64 q/CTA (256 CTAs,
// 2 CTAs/SM), 64-key tiles. Q/K tile row stride = 24 halves, V/P stride = 72
// halves: conflict-free LDSM phases. PV pipelined one tile behind QK/softmax
// with double-buffered P.
// ---------------------------------------------------------------------------

__device__ float g_q[4 * 16 * 4096];             // conv out (b,c16,n) fp32
__device__ float g_k[4 * 16 * 4096];
__device__ __half g_qt[4 * 64 * 64 * 24];        // Q tiles [b][qt64][row64][24]
__device__ __half g_kt[4 * 64 * 64 * 24];        // K tiles [b][nt][key64][24]
__device__ __half g_vt[4 * 64 * 256 * 72];       // V tiles [b][nt][ch256][72]

// m16n8k16 f16 MMA, fp32 accum (baseline sm_80 PTX -> HMMA on sm_103)
__device__ __forceinline__ void mma16816(float d[4],
    uint32_t a0, uint32_t a1, uint32_t a2, uint32_t a3,
    uint32_t b0, uint32_t b1)
{
    asm volatile(
        "mma.sync.aligned.m16n8k16.row.col.f32.f16.f16.f32 "
        "{%0,%1,%2,%3}, {%4,%5,%6,%7}, {%8,%9}, {%0,%1,%2,%3};"
        : "+f"(d[0]), "+f"(d[1]), "+f"(d[2]), "+f"(d[3])
        : "r"(a0), "r"(a1), "r"(a2), "r"(a3), "r"(b0), "r"(b1));
}
__device__ __forceinline__ void ldsm_x4(uint32_t& r0, uint32_t& r1,
                                        uint32_t& r2, uint32_t& r3, uint32_t a) {
    asm volatile("ldmatrix.sync.aligned.m8n8.x4.shared.b16 {%0,%1,%2,%3}, [%4];"
                 : "=r"(r0), "=r"(r1), "=r"(r2), "=r"(r3) : "r"(a));
}
__device__ __forceinline__ void ldsm_x4_t(uint32_t& r0, uint32_t& r1,
                                          uint32_t& r2, uint32_t& r3, uint32_t a) {
    asm volatile("ldmatrix.sync.aligned.m8n8.x4.trans.shared.b16 {%0,%1,%2,%3}, [%4];"
                 : "=r"(r0), "=r"(r1), "=r"(r2), "=r"(r3) : "r"(a));
}
__device__ __forceinline__ uint32_t smem_u32(const void* p) {
    uint32_t a;
    asm("{ .reg .u64 t; cvta.to.shared.u64 t, %1; cvt.u32.u64 %0, t; }"
        : "=r"(a) : "l"(p));
    return a;
}
__device__ __forceinline__ void cp_async16(uint32_t sm, const void* g) {
    asm volatile("cp.async.cg.shared.global [%0], [%1], 16;"
                 :: "r"(sm), "l"(g) : "memory");
}
#define CP_COMMIT() asm volatile("cp.async.commit_group;" ::: "memory")
#define CP_WAIT1()  asm volatile("cp.async.wait_group 1;" ::: "memory")

// ===========================================================================
// Kernel 1: q = conv1x3(x), k = conv3x1(x)  (raw + bias, fp32). 512 threads.
// ===========================================================================
__global__ __launch_bounds__(512) void qk_conv_kernel(
    const float* __restrict__ x,
    const float* __restrict__ wq, const float* __restrict__ bq,
    const float* __restrict__ wk, const float* __restrict__ bk)
{
    __shared__ float xs[3 * 32 * 66];
    __shared__ float wqs[16 * 32 * 3];
    __shared__ float wks[16 * 32 * 3];

    int b = blockIdx.x >> 6;
    int h = blockIdx.x & 63;
    int t = threadIdx.x;
    int co = t >> 5;        // 0..15
    int wb = t & 31;        // w base

    float qa[2] = {0.f, 0.f};
    float ka[2] = {0.f, 0.f};

    for (int ci0 = 0; ci0 < 256; ci0 += 32) {
        __syncthreads();
        if (t < 96) { xs[t * 66 + 0] = 0.f; xs[t * 66 + 65] = 0.f; }
        for (int idx = t; idx < 3 * 32 * 64; idx += 512) {
            int w = idx & 63;
            int rc = idx >> 6;
            int dh = rc >> 5;
            int ci = rc & 31;
            int hh = h + dh - 1;
            float v = 0.f;
            if (hh >= 0 && hh < 64)
                v = x[((b * 256 + ci0 + ci) * 64 + hh) * 64 + w];
            xs[rc * 66 + 1 + w] = v;
        }
        for (int idx = t; idx < 16 * 32 * 3; idx += 512) {
            int kk = idx % 3;
            int rc = idx / 3;
            int cco = rc >> 5;
            int ci = rc & 31;
            wqs[idx] = wq[(cco * 256 + ci0 + ci) * 3 + kk];
            wks[idx] = wk[(cco * 256 + ci0 + ci) * 3 + kk];
        }
        __syncthreads();

        for (int ci = 0; ci < 32; ci++) {
            float q0 = wqs[(co * 32 + ci) * 3 + 0];
            float q1 = wqs[(co * 32 + ci) * 3 + 1];
            float q2 = wqs[(co * 32 + ci) * 3 + 2];
            float k0 = wks[(co * 32 + ci) * 3 + 0];
            float k1 = wks[(co * 32 + ci) * 3 + 1];
            float k2 = wks[(co * 32 + ci) * 3 + 2];
            const float* x0 = &xs[(0 * 32 + ci) * 66];
            const float* x1 = &xs[(1 * 32 + ci) * 66];
            const float* x2 = &xs[(2 * 32 + ci) * 66];
#pragma unroll
            for (int r = 0; r < 2; r++) {
                int w = wb + 32 * r;
                float xm = x1[w];
                float xc = x1[w + 1];
                float xp = x1[w + 2];
                qa[r] += q0 * xm + q1 * xc + q2 * xp;
                ka[r] += k0 * x0[w + 1] + k1 * xc + k2 * x2[w + 1];
            }
        }
    }
    float bqv = bq[co], bkv = bk[co];
    int base = (b * 16 + co) * 4096 + h * 64;
#pragma unroll
    for (int r = 0; r < 2; r++) {
        int w = wb + 32 * r;
        g_q[base + w] = qa[r] + bqv;
        g_k[base + w] = ka[r] + bkv;
    }
}

// ===========================================================================
// Kernel 2: FRN + Mish, pack f16 Q/K tile images (float4-vectorized).
// ===========================================================================
__global__ __launch_bounds__(256) void frn_mish_pack_kernel(
    const float* __restrict__ eps_q, const float* __restrict__ eps_k)
{
    __shared__ float red[256];
    __shared__ float sc_s;
    int id = blockIdx.x;                 // 0..127
    int branch = id >> 6;
    int b = (id >> 4) & 3;
    int c = id & 15;
    const float* p = (branch ? g_k : g_q) + (b * 16 + c) * 4096;
    float eps = fabsf(branch ? eps_k[c] : eps_q[c]);
    int t = threadIdx.x;

    float s = 0.f;
    for (int i = t * 4; i < 4096; i += 1024) {
        float4 v = *(const float4*)(p + i);
        s += v.x * v.x + v.y * v.y + v.z * v.z + v.w * v.w;
    }
    red[t] = s;
    __syncthreads();
    for (int off = 128; off > 0; off >>= 1) {
        if (t < off) red[t] += red[t + off];
        __syncthreads();
    }
    if (t == 0) sc_s = rsqrtf(red[0] / 4096.f + eps);
    __syncthreads();
    float sc = sc_s;
    for (int i = t * 4; i < 4096; i += 1024) {
        float4 v4 = *(const float4*)(p + i);
        float vv[4] = {v4.x, v4.y, v4.z, v4.w};
#pragma unroll
        for (int e = 0; e < 4; e++) {
            float v = vv[e] * sc;
            float sp = (v > 20.f) ? v : log1pf(expf(v));
            float m = v * tanhf(sp);
            __half hi = __float2half_rn(m);
            int ii = i + e;
            int row = ii & 63, ntl = ii >> 6;
            if (!branch)
                g_qt[((size_t)(b * 64 + ntl) * 64 + row) * 24 + c] = hi;
            else
                g_kt[((size_t)(b * 64 + ntl) * 64 + row) * 24 + c] = hi;
        }
    }
}

// ===========================================================================
// Kernel 3: v = wv @ x + bv via HMMA (f16 inputs, fp32 accum).
// ===========================================================================
#define VG_XOFF (256 * 72)
#define VG_SMEM ((256 * 72 + 64 * 136) * 2)

__global__ __launch_bounds__(512) void v_gemm_mma_kernel(
    const float* __restrict__ x,
    const float* __restrict__ wv, const float* __restrict__ bv)
{
    extern __shared__ __half vsh[];
    __half* Ws = vsh;
    __half* Xs = vsh + VG_XOFF;
    const int b = blockIdx.y, nblk = blockIdx.x, n0 = nblk * 128;
    const int t = threadIdx.x, w = t >> 5, lane = t & 31;
    const int g = lane >> 3, r8 = lane & 7;
    const int cw = w * 16;
    const uint32_t shb = smem_u32(vsh);
    const uint32_t aA = shb + ((cw + (g & 1) * 8 + r8) * 72 + (g >> 1) * 8) * 2;
    const uint32_t aB = shb + VG_XOFF * 2 + ((g & 1) * 8 + r8) * 136 * 2 + (g >> 1) * 16;

    float Acc[16][4];
#pragma unroll
    for (int nb = 0; nb < 16; nb++)
        Acc[nb][0] = Acc[nb][1] = Acc[nb][2] = Acc[nb][3] = 0.f;

    for (int kc = 0; kc < 4; kc++) {
        __syncthreads();
        for (int idx = t; idx < 4096; idx += 512) {
            int row = idx >> 4, col4 = (idx & 15) * 4;
            float4 v = *(const float4*)(wv + row * 256 + kc * 64 + col4);
            uint2 hh;
            __half2 h0 = __floats2half2_rn(v.x, v.y);
            __half2 h1 = __floats2half2_rn(v.z, v.w);
            hh.x = *reinterpret_cast<uint32_t*>(&h0);
            hh.y = *reinterpret_cast<uint32_t*>(&h1);
            *reinterpret_cast<uint2*>(Ws + row * 72 + col4) = hh;
        }
        for (int idx = t; idx < 2048; idx += 512) {
            int row = idx >> 5, col4 = (idx & 31) * 4;
            float4 v = *(const float4*)(x + (size_t)(b * 256 + kc * 64 + row) * 4096 + n0 + col4);
            uint2 hh;
            __half2 h0 = __floats2half2_rn(v.x, v.y);
            __half2 h1 = __floats2half2_rn(v.z, v.w);
            hh.x = *reinterpret_cast<uint32_t*>(&h0);
            hh.y = *reinterpret_cast<uint32_t*>(&h1);
            *reinterpret_cast<uint2*>(Xs + row * 136 + col4) = hh;
        }
        __syncthreads();
#pragma unroll
        for (int s = 0; s < 4; s++) {
            uint32_t a0, a1, a2, a3;
            ldsm_x4(a0, a1, a2, a3, aA + s * 32);
#pragma unroll
            for (int p = 0; p < 8; p++) {
                uint32_t b0, b1, b2, b3;
                ldsm_x4_t(b0, b1, b2, b3, aB + s * (16 * 136 * 2) + p * 32);
                mma16816(Acc[2 * p], a0, a1, a2, a3, b0, b1);
                mma16816(Acc[2 * p + 1], a0, a1, a2, a3, b2, b3);
            }
        }
    }

    const int c0 = cw + (lane >> 2);
    const float bv0 = bv[c0], bv1 = bv[c0 + 8];
#pragma unroll
    for (int nb = 0; nb < 16; nb++) {
        int nl = nb * 8 + (lane & 3) * 2;
        int ntl = nblk * 2 + (nl >> 6);
        int key = nl & 63;
        __half* vb = g_vt + (size_t)(b * 64 + ntl) * 256 * 72;
        __half2 h0 = __floats2half2_rn(Acc[nb][0] + bv0, Acc[nb][1] + bv0);
        __half2 h1 = __floats2half2_rn(Acc[nb][2] + bv1, Acc[nb][3] + bv1);
        *reinterpret_cast<uint32_t*>(vb + (size_t)c0 * 72 + key) =
            *reinterpret_cast<uint32_t*>(&h0);
        *reinterpret_cast<uint32_t*>(vb + (size_t)(c0 + 8) * 72 + key) =
            *reinterpret_cast<uint32_t*>(&h1);
    }
}

// ===========================================================================
// Kernel 4: pipelined single-pass online-softmax HMMA flash attention.
// 64 queries/CTA, 256 threads / 8 warps, 2 CTAs per SM.
// Schedule per tile i: wait/sync -> issue K(i+1) -> QK(i) -> PV(i-1)
//   -> sync -> issue V(i+1) -> softmax(i) [rescale O AFTER PV(i-1): exact].
// P double-buffered; two full barriers per tile, no named barriers.
// smem(halves): Q[0,1536) K2[1536,4608) V2[4608,41472) P2[41472,50688)
// ===========================================================================
#define SM_KO(buf) (1536 + (buf) * 1536)
#define SM_VO(buf) (4608 + (buf) * 18432)
#define SM_PO(buf) (41472 + (buf) * 4608)
#define TOT_HALVES 50688
#define ATTN_SMEM_BYTES (TOT_HALVES * 2 + 512 * 4)

__global__ __launch_bounds__(256, 2) void attn_mma_kernel(
    const float* __restrict__ x, const float* __restrict__ gamma,
    float* __restrict__ out)
{
    extern __shared__ __half sh[];
    float* s_pmax = (float*)(sh + TOT_HALVES);   // [4][64]
    float* s_lsum = s_pmax + 256;                // [4][64]

    const int b  = blockIdx.y;
    const int qt = blockIdx.x;
    const int j0 = qt * 64;
    const int t  = threadIdx.x;
    const int w  = t >> 5, lane = t & 31;
    const int gr = lane >> 2, ci = lane & 3;
    const int g  = lane >> 3, r8 = lane & 7;
    const int a  = w & 1;                        // row band (rows 32a..32a+31)
    const int kq = w >> 1;                       // key quarter / channel quarter
    const int rb = a * 32;
    const float L2E = 1.44269504f;
    const uint32_t shb = smem_u32(sh);

    // LDSM lane addresses
    const uint32_t aQ = shb + ((rb + (g & 1) * 8 + r8) * 24 + (g >> 1) * 8) * 2;
    const uint32_t oK = ((kq * 16 + (g >> 1) * 8 + r8) * 24 + (g & 1) * 8) * 2;
    const uint32_t pfo = ((rb + (g & 1) * 8 + r8) * 72 + (g >> 1) * 8) * 2;
    const uint32_t aP0 = shb + SM_PO(0) * 2 + pfo;
    const uint32_t aP1 = shb + SM_PO(1) * 2 + pfo;
    const uint32_t oV = ((kq * 64 + (g >> 1) * 8 + r8) * 72 + (g & 1) * 8) * 2;

    const float4* kgb = (const float4*)(g_kt + (size_t)(b * 64) * 1536);
    const float4* vgb = (const float4*)(g_vt + (size_t)(b * 64) * 18432);
    const uint32_t kd0 = shb + SM_KO(0) * 2, kd1 = shb + SM_KO(1) * 2;
    const uint32_t vd0 = shb + SM_VO(0) * 2, vd1 = shb + SM_VO(1) * 2;

    // prologue: group(K0), group(V0); Q staged with plain loads
    if (t < 192) cp_async16(kd0 + t * 16, kgb + t);
    CP_COMMIT();
#pragma unroll
    for (int j = 0; j < 9; j++) {
        int i4 = t + j * 256;
        cp_async16(vd0 + i4 * 16, vgb + i4);
    }
    CP_COMMIT();
    {
        const float4* qg = (const float4*)(g_qt + (size_t)(b * 64 + qt) * 1536);
        float4* qd = (float4*)sh;
        if (t < 192) qd[t] = qg[t];
    }
    __syncthreads();

    // hoisted loop-invariant Q fragments (32 rows x 16 slots per warp)
    uint32_t qf[2][4];
    ldsm_x4(qf[0][0], qf[0][1], qf[0][2], qf[0][3], aQ);
    ldsm_x4(qf[1][0], qf[1][1], qf[1][2], qf[1][3], aQ + 768);

    float O[2][8][4];
#pragma unroll
    for (int m = 0; m < 2; m++)
#pragma unroll
        for (int nb = 0; nb < 8; nb++)
            O[m][nb][0] = O[m][nb][1] = O[m][nb][2] = O[m][nb][3] = 0.f;
    float mrun[4] = {-1e30f, -1e30f, -1e30f, -1e30f};
    float lrun[4] = {0.f, 0.f, 0.f, 0.f};
    const int r0 = rb + gr;                      // rows r0, +8, +16, +24

    for (int ntl = 0; ntl < 64; ntl++) {
        CP_WAIT1();          // K(ntl) + all older arrived; V(ntl) may fly
        __syncthreads();     // also publishes P(ntl-1) written last iteration

        // issue K(ntl+1)
        {
            int nn = ntl + 1;
            if (nn < 64 && t < 192)
                cp_async16(((nn & 1) ? kd1 : kd0) + t * 16, kgb + nn * 192 + t);
        }
        CP_COMMIT();

        // ---- QK(ntl): 32 rows x 16 keys ----
        const uint32_t kbyte = (ntl & 1) ? kd1 : kd0;
        float S[4][4];
#pragma unroll
        for (int i = 0; i < 4; i++) S[i][0] = S[i][1] = S[i][2] = S[i][3] = 0.f;
        {
            uint32_t b0, b1, b2, b3;
            ldsm_x4(b0, b1, b2, b3, kbyte + oK);
            mma16816(S[0], qf[0][0], qf[0][1], qf[0][2], qf[0][3], b0, b1);
            mma16816(S[1], qf[0][0], qf[0][1], qf[0][2], qf[0][3], b2, b3);
            mma16816(S[2], qf[1][0], qf[1][1], qf[1][2], qf[1][3], b0, b1);
            mma16816(S[3], qf[1][0], qf[1][1], qf[1][2], qf[1][3], b2, b3);
        }
        // per-warp partial row max -> smem
        float pm[4];
        pm[0] = fmaxf(fmaxf(S[0][0], S[0][1]), fmaxf(S[1][0], S[1][1]));
        pm[1] = fmaxf(fmaxf(S[0][2], S[0][3]), fmaxf(S[1][2], S[1][3]));
        pm[2] = fmaxf(fmaxf(S[2][0], S[2][1]), fmaxf(S[3][0], S[3][1]));
        pm[3] = fmaxf(fmaxf(S[2][2], S[2][3]), fmaxf(S[3][2], S[3][3]));
#pragma unroll
        for (int j = 0; j < 4; j++) {
            pm[j] = fmaxf(pm[j], __shfl_xor_sync(0xffffffffu, pm[j], 1));
            pm[j] = fmaxf(pm[j], __shfl_xor_sync(0xffffffffu, pm[j], 2));
        }
        if (ci == 0) {
#pragma unroll
            for (int j = 0; j < 4; j++)
                s_pmax[kq * 64 + r0 + j * 8] = pm[j];
        }

        // ---- PV(ntl-1): 32 rows x 64 channels (overlaps partner skew) ----
        if (ntl > 0) {
            const uint32_t vbyte = ((ntl - 1) & 1) ? vd1 : vd0;
            const uint32_t aPb = ((ntl - 1) & 1) ? aP1 : aP0;
#pragma unroll
            for (int s = 0; s < 4; s++) {
                uint32_t pa0, pa1, pa2, pa3, pb0, pb1, pb2, pb3;
                ldsm_x4(pa0, pa1, pa2, pa3, aPb + s * 32);
                ldsm_x4(pb0, pb1, pb2, pb3, aPb + 2304 + s * 32);
#pragma unroll
                for (int p = 0; p < 4; p++) {
                    uint32_t b0, b1, b2, b3;
                    ldsm_x4(b0, b1, b2, b3, vbyte + oV + p * 2304 + s * 32);
                    mma16816(O[0][2 * p],     pa0, pa1, pa2, pa3, b0, b1);
                    mma16816(O[0][2 * p + 1], pa0, pa1, pa2, pa3, b2, b3);
                    mma16816(O[1][2 * p],     pb0, pb1, pb2, pb3, b0, b1);
                    mma16816(O[1][2 * p + 1], pb0, pb1, pb2, pb3, b2, b3);
                }
            }
        }
        __syncthreads();     // pmax visible; V(ntl-1) buffer free

        // issue V(ntl+1) into the freed buffer
        {
            int nn = ntl + 1;
            if (nn < 64) {
                uint32_t vdn = (nn & 1) ? vd1 : vd0;
                const float4* vsrc = vgb + (size_t)nn * 2304;
#pragma unroll
                for (int j = 0; j < 9; j++) {
                    int i4 = t + j * 256;
                    cp_async16(vdn + i4 * 16, vsrc + i4);
                }
            }
        }
        CP_COMMIT();

        // ---- softmax(ntl): combined max, rescale O (post-PV: exact), P ----
        float sc[4], mL[4];
#pragma unroll
        for (int j = 0; j < 4; j++) {
            int r = r0 + j * 8;
            float mn = fmaxf(fmaxf(s_pmax[r], s_pmax[64 + r]),
                             fmaxf(s_pmax[128 + r], s_pmax[192 + r]));
            mn = fmaxf(mrun[j], mn);
            sc[j] = exp2f((mrun[j] - mn) * L2E);
            mrun[j] = mn;
            mL[j] = mn * L2E;
        }
        bool need = (sc[0] != 1.f) | (sc[1] != 1.f) | (sc[2] != 1.f) | (sc[3] != 1.f);
        if (__any_sync(0xffffffffu, need)) {
#pragma unroll
            for (int m = 0; m < 2; m++)
#pragma unroll
                for (int nb = 0; nb < 8; nb++) {
                    O[m][nb][0] *= sc[2 * m]; O[m][nb][1] *= sc[2 * m];
                    O[m][nb][2] *= sc[2 * m + 1]; O[m][nb][3] *= sc[2 * m + 1];
                }
        }
        __half* Psb = sh + ((ntl & 1) ? SM_PO(1) : SM_PO(0));
        float tl[4] = {0.f, 0.f, 0.f, 0.f};
#pragma unroll
        for (int m = 0; m < 2; m++) {
#pragma unroll
            for (int n = 0; n < 2; n++) {
                int idx = m * 2 + n;
                float y0 = fmaf(S[idx][0], L2E, -mL[2 * m]);
                float y1 = fmaf(S[idx][1], L2E, -mL[2 * m]);
                float y2 = fmaf(S[idx][2], L2E, -mL[2 * m + 1]);
                float y3 = fmaf(S[idx][3], L2E, -mL[2 * m + 1]);
                __half2 h0 = h2exp2(__floats2half2_rn(y0, y1));
                __half2 h1 = h2exp2(__floats2half2_rn(y2, y3));
                *reinterpret_cast<uint32_t*>(
                    Psb + (rb + 16 * m + gr) * 72 + kq * 16 + n * 8 + ci * 2) =
                    *reinterpret_cast<uint32_t*>(&h0);
                *reinterpret_cast<uint32_t*>(
                    Psb + (rb + 16 * m + gr + 8) * 72 + kq * 16 + n * 8 + ci * 2) =
                    *reinterpret_cast<uint32_t*>(&h1);
                tl[2 * m]     += __low2float(h0) + __high2float(h0);
                tl[2 * m + 1] += __low2float(h1) + __high2float(h1);
            }
        }
#pragma unroll
        for (int j = 0; j < 4; j++) lrun[j] = lrun[j] * sc[j] + tl[j];
    }

    // ---- drain: PV(63) ----
    __syncthreads();         // P(63) visible
    {
        const uint32_t vbyte = vd1;     // 63 & 1 == 1
        const uint32_t aPb = aP1;
#pragma unroll
        for (int s = 0; s < 4; s++) {
            uint32_t pa0, pa1, pa2, pa3, pb0, pb1, pb2, pb3;
            ldsm_x4(pa0, pa1, pa2, pa3, aPb + s * 32);
            ldsm_x4(pb0, pb1, pb2, pb3, aPb + 2304 + s * 32);
#pragma unroll
            for (int p = 0; p < 4; p++) {
                uint32_t b0, b1, b2, b3;
                ldsm_x4(b0, b1, b2, b3, vbyte + oV + p * 2304 + s * 32);
                mma16816(O[0][2 * p],     pa0, pa1, pa2, pa3, b0, b1);
                mma16816(O[0][2 * p + 1], pa0, pa1, pa2, pa3, b2, b3);
                mma16816(O[1][2 * p],     pb0, pb1, pb2, pb3, b0, b1);
                mma16816(O[1][2 * p + 1], pb0, pb1, pb2, pb3, b2, b3);
            }
        }
    }

    // combine l across the 4 key-quarter warps of each row band
#pragma unroll
    for (int j = 0; j < 4; j++) {
        lrun[j] += __shfl_xor_sync(0xffffffffu, lrun[j], 1);
        lrun[j] += __shfl_xor_sync(0xffffffffu, lrun[j], 2);
    }
    if (ci == 0) {
#pragma unroll
        for (int j = 0; j < 4; j++)
            s_lsum[kq * 64 + r0 + j * 8] = lrun[j];
    }
    __syncthreads();

    // epilogue: out = gamma*O/l + x
    const float gm = gamma[0];
    float li[4];
#pragma unroll
    for (int j = 0; j < 4; j++) {
        int r = r0 + j * 8;
        li[j] = gm / (s_lsum[r] + s_lsum[64 + r] + s_lsum[128 + r] + s_lsum[192 + r]);
    }
#pragma unroll
    for (int m = 0; m < 2; m++) {
        const int row = j0 + rb + 16 * m + gr;
#pragma unroll
        for (int nb = 0; nb < 8; nb++) {
            int ch = kq * 64 + nb * 8 + ci * 2;
            size_t i0 = ((size_t)(b * 256 + ch)) * 4096 + row;
            out[i0]            = O[m][nb][0] * li[2 * m] + x[i0];
            out[i0 + 4096]     = O[m][nb][1] * li[2 * m] + x[i0 + 4096];
            out[i0 + 8]        = O[m][nb][2] * li[2 * m + 1] + x[i0 + 8];
            out[i0 + 4096 + 8] = O[m][nb][3] * li[2 * m + 1] + x[i0 + 4096 + 8];
        }
    }
}

// ===========================================================================
extern "C" void kernel_launch(void* const* d_in, const int* in_sizes, int n_in,
                              void* d_out, int out_size)
{
    const float* x     = (const float*)d_in[0];
    const float* wq    = (const float*)d_in[1];
    const float* bq    = (const float*)d_in[2];
    const float* wk    = (const float*)d_in[3];
    const float* bk    = (const float*)d_in[4];
    const float* wv    = (const float*)d_in[5];
    const float* bv    = (const float*)d_in[6];
    const float* gamma = (const float*)d_in[7];
    const float* eps_q = (const float*)d_in[8];
    const float* eps_k = (const float*)d_in[9];
    float* out = (float*)d_out;

    qk_conv_kernel<<<256, 512>>>(x, wq, bq, wk, bk);
    frn_mish_pack_kernel<<<128, 256>>>(eps_q, eps_k);

    cudaFuncSetAttribute(v_gemm_mma_kernel,
                         cudaFuncAttributeMaxDynamicSharedMemorySize, VG_SMEM);
    v_gemm_mma_kernel<<<dim3(32, 4), 512, VG_SMEM>>>(x, wv, bv);

    cudaFuncSetAttribute(attn_mma_kernel,
                         cudaFuncAttributeMaxDynamicSharedMemorySize,
                         ATTN_SMEM_BYTES);
    attn_mma_kernel<<<dim3(64, 4), 256, ATTN_SMEM_BYTES>>>(x, gamma, out);
}

// round 14
// speedup vs baseline: 1.1573x; 1.1573x over previous
#include <cuda_runtime.h>
#include <cuda_fp16.h>
#include <math.h>
#include <stdint.h>

// ---------------------------------------------------------------------------
// B=4, C=256, C16=16, H=W=64, N=4096. Attention: 64 q/CTA (256 CTAs,
// 2 CTAs/SM), 64-key tiles. Q/K tile row stride = 24 halves, V/P stride = 72
// halves: conflict-free LDSM phases.  qk conv now runs on HMMA via a 6-tap
// im2col GEMM (A = packed q/k weights, B built in smem from 3 x-rows).
// ---------------------------------------------------------------------------

__device__ __half g_qr[4 * 16 * 4096];           // raw conv out q (b,c16,n) f16
__device__ __half g_kr[4 * 16 * 4096];           // raw conv out k
__device__ __half g_apk[8 * 32 * 200];           // packed qk weights [chunk][co32][200]
__device__ __half g_qt[4 * 64 * 64 * 24];        // Q tiles [b][qt64][row64][24]
__device__ __half g_kt[4 * 64 * 64 * 24];        // K tiles [b][nt][key64][24]
__device__ __half g_vt[4 * 64 * 256 * 72];       // V tiles [b][nt][ch256][72]

// m16n8k16 f16 MMA, fp32 accum (baseline sm_80 PTX -> HMMA on sm_103)
__device__ __forceinline__ void mma16816(float d[4],
    uint32_t a0, uint32_t a1, uint32_t a2, uint32_t a3,
    uint32_t b0, uint32_t b1)
{
    asm volatile(
        "mma.sync.aligned.m16n8k16.row.col.f32.f16.f16.f32 "
        "{%0,%1,%2,%3}, {%4,%5,%6,%7}, {%8,%9}, {%0,%1,%2,%3};"
        : "+f"(d[0]), "+f"(d[1]), "+f"(d[2]), "+f"(d[3])
        : "r"(a0), "r"(a1), "r"(a2), "r"(a3), "r"(b0), "r"(b1));
}
__device__ __forceinline__ void ldsm_x4(uint32_t& r0, uint32_t& r1,
                                        uint32_t& r2, uint32_t& r3, uint32_t a) {
    asm volatile("ldmatrix.sync.aligned.m8n8.x4.shared.b16 {%0,%1,%2,%3}, [%4];"
                 : "=r"(r0), "=r"(r1), "=r"(r2), "=r"(r3) : "r"(a));
}
__device__ __forceinline__ void ldsm_x4_t(uint32_t& r0, uint32_t& r1,
                                          uint32_t& r2, uint32_t& r3, uint32_t a) {
    asm volatile("ldmatrix.sync.aligned.m8n8.x4.trans.shared.b16 {%0,%1,%2,%3}, [%4];"
                 : "=r"(r0), "=r"(r1), "=r"(r2), "=r"(r3) : "r"(a));
}
__device__ __forceinline__ uint32_t smem_u32(const void* p) {
    uint32_t a;
    asm("{ .reg .u64 t; cvta.to.shared.u64 t, %1; cvt.u32.u64 %0, t; }"
        : "=r"(a) : "l"(p));
    return a;
}
__device__ __forceinline__ void cp_async16(uint32_t sm, const void* g) {
    asm volatile("cp.async.cg.shared.global [%0], [%1], 16;"
                 :: "r"(sm), "l"(g) : "memory");
}
#define CP_COMMIT() asm volatile("cp.async.commit_group;" ::: "memory")
#define CP_WAIT0()  asm volatile("cp.async.wait_group 0;" ::: "memory")
#define BAR4(id) asm volatile("bar.sync %0, 128;" :: "r"(id) : "memory")

// ===========================================================================
// Kernel 0: pack qk conv weights into the A matrix image.
// A[chunk][co][k = tap*32+ci]: co<16 -> q taps 0..2 (1x3), co>=16 -> k taps
// 3..5 (3x1), zeros elsewhere. Stride 200 halves.
// ===========================================================================
__global__ __launch_bounds__(256) void qk_prepack_kernel(
    const float* __restrict__ wq, const float* __restrict__ wk)
{
    int idx = blockIdx.x * 256 + threadIdx.x;
    if (idx >= 8 * 32 * 192) return;
    int kc = idx / (32 * 192);
    int rem = idx % (32 * 192);
    int co = rem / 192;
    int kk = rem % 192;
    int tap = kk >> 5, cc = kk & 31;
    float v = 0.f;
    if (co < 16) {
        if (tap < 3) v = wq[(co * 256 + kc * 32 + cc) * 3 + tap];
    } else {
        if (tap >= 3) v = wk[((co - 16) * 256 + kc * 32 + cc) * 3 + (tap - 3)];
    }
    g_apk[(kc * 32 + co) * 200 + kk] = __float2half_rn(v);
}

// ===========================================================================
// Kernel 1: q = conv1x3(x), k = conv3x1(x) via HMMA im2col GEMM.
// Grid 256 = (b*64 + h). 256 threads / 8 warps: warp = (m = co-half, p = w16).
// Per chunk (32 ci): stage A (from g_apk) + 3 x-rows f16 (stride 70,
// conflict-free), build B[w64][k192] (stride 200) tap-per-warp, 12 k-steps
// of MMA. Output raw f16 q/k (+bias) to g_qr/g_kr.
// ===========================================================================
#define QKC_A 0
#define QKC_B (32 * 200)
#define QKC_X (32 * 200 + 64 * 200)
#define QKC_HALVES (32 * 200 + 64 * 200 + 96 * 70)
#define QKC_BYTES (QKC_HALVES * 2)

__global__ __launch_bounds__(256) void qk_conv_mma_kernel(
    const float* __restrict__ x,
    const float* __restrict__ bq, const float* __restrict__ bk)
{
    extern __shared__ __half qs[];
    __half* As = qs + QKC_A;
    __half* Bs = qs + QKC_B;
    __half* Xs = qs + QKC_X;

    const int b = blockIdx.x >> 6;
    const int h = blockIdx.x & 63;
    const int t = threadIdx.x;
    const int w8 = t >> 5, lane = t & 31;
    const int gr = lane >> 2, ci4 = lane & 3;
    const int g = lane >> 3, r8 = lane & 7;
    const int m = w8 & 1;          // 0 -> q co rows, 1 -> k co rows
    const int p = w8 >> 1;         // w-16 block 0..3
    const uint32_t shb = smem_u32(qs);
    const uint32_t aA = shb + QKC_A * 2 +
        ((m * 16 + (g & 1) * 8 + r8) * 200 + (g >> 1) * 8) * 2;
    const uint32_t bB = shb + QKC_B * 2 +
        ((p * 16 + (g >> 1) * 8 + r8) * 200 + (g & 1) * 8) * 2;

    float D0[4] = {0.f, 0.f, 0.f, 0.f};
    float D1[4] = {0.f, 0.f, 0.f, 0.f};

    for (int kc = 0; kc < 8; kc++) {
        __syncthreads();
        // stage A chunk (3200 words)
        {
            const uint32_t* apk = (const uint32_t*)(g_apk + kc * 6400);
            uint32_t* as32 = (uint32_t*)As;
            for (int i = t; i < 3200; i += 256) as32[i] = apk[i];
        }
        // stage 3 x-rows f16 [96][70], cols 1..64 data, 0/65 zero pads
        if (t < 96) { Xs[t * 70] = __float2half_rn(0.f); Xs[t * 70 + 65] = __float2half_rn(0.f); }
        for (int i = t; i < 6144; i += 256) {
            int w = i & 63, rc = i >> 6;
            int dh = rc >> 5, cc = rc & 31;
            int hh = h + dh - 1;
            float v = 0.f;
            if (hh >= 0 && hh < 64)
                v = x[((b * 256 + kc * 32 + cc) * 64 + hh) * 64 + w];
            Xs[rc * 70 + 1 + w] = __float2half_rn(v);
        }
        __syncthreads();
        // build B[w][k]: taps 0..2 = row h shifted by w-1..w+1; taps 3..5 = rows h-1..h+1
        if (t < 192) {
            int tap = t >> 5, cc = t & 31;
            const __half* src = (tap < 3) ? (Xs + (32 + cc) * 70 + tap)
                                          : (Xs + ((tap - 3) * 32 + cc) * 70 + 1);
            __half* dst = Bs + t;
#pragma unroll 16
            for (int w = 0; w < 64; w++) dst[w * 200] = src[w];
        }
        __syncthreads();
#pragma unroll
        for (int s = 0; s < 12; s++) {
            uint32_t a0, a1, a2, a3, b0, b1, b2, b3;
            ldsm_x4(a0, a1, a2, a3, aA + s * 32);
            ldsm_x4(b0, b1, b2, b3, bB + s * 32);
            mma16816(D0, a0, a1, a2, a3, b0, b1);
            mma16816(D1, a0, a1, a2, a3, b2, b3);
        }
    }

    // epilogue: + bias, f16 raw outputs
    const float* bias = m ? bk : bq;
    __half* dstb = m ? g_kr : g_qr;
    const float bv0 = bias[gr], bv1 = bias[gr + 8];
    const size_t base0 = ((size_t)(b * 16 + gr)) * 4096 + h * 64 + p * 16 + ci4 * 2;
    const size_t base1 = ((size_t)(b * 16 + gr + 8)) * 4096 + h * 64 + p * 16 + ci4 * 2;
    __half2 h00 = __floats2half2_rn(D0[0] + bv0, D0[1] + bv0);
    __half2 h01 = __floats2half2_rn(D0[2] + bv1, D0[3] + bv1);
    __half2 h10 = __floats2half2_rn(D1[0] + bv0, D1[1] + bv0);
    __half2 h11 = __floats2half2_rn(D1[2] + bv1, D1[3] + bv1);
    *reinterpret_cast<__half2*>(dstb + base0)     = h00;
    *reinterpret_cast<__half2*>(dstb + base1)     = h01;
    *reinterpret_cast<__half2*>(dstb + base0 + 8) = h10;
    *reinterpret_cast<__half2*>(dstb + base1 + 8) = h11;
}

// ===========================================================================
// Kernel 2: FRN + Mish on raw f16 q/k, pack f16 Q/K tile images.
// ===========================================================================
__global__ __launch_bounds__(256) void frn_mish_pack_kernel(
    const float* __restrict__ eps_q, const float* __restrict__ eps_k)
{
    __shared__ float red[256];
    __shared__ float sc_s;
    int id = blockIdx.x;                 // 0..127
    int branch = id >> 6;
    int b = (id >> 4) & 3;
    int c = id & 15;
    const __half* p = (branch ? g_kr : g_qr) + (size_t)(b * 16 + c) * 4096;
    float eps = fabsf(branch ? eps_k[c] : eps_q[c]);
    int t = threadIdx.x;

    float s = 0.f;
    for (int i = t; i < 2048; i += 256) {
        float2 f = __half22float2(((const __half2*)p)[i]);
        s += f.x * f.x + f.y * f.y;
    }
    red[t] = s;
    __syncthreads();
    for (int off = 128; off > 0; off >>= 1) {
        if (t < off) red[t] += red[t + off];
        __syncthreads();
    }
    if (t == 0) sc_s = rsqrtf(red[0] / 4096.f + eps);
    __syncthreads();
    float sc = sc_s;
    for (int i = t; i < 4096; i += 256) {
        float v = __half2float(p[i]) * sc;
        float sp = (v > 20.f) ? v : log1pf(expf(v));
        float mm = v * tanhf(sp);
        __half hi = __float2half_rn(mm);
        int row = i & 63, ntl = i >> 6;
        if (!branch)
            g_qt[((size_t)(b * 64 + ntl) * 64 + row) * 24 + c] = hi;
        else
            g_kt[((size_t)(b * 64 + ntl) * 64 + row) * 24 + c] = hi;
    }
}

// ===========================================================================
// Kernel 3: v = wv @ x + bv via HMMA (f16 inputs, fp32 accum).
// ===========================================================================
#define VG_XOFF (256 * 72)
#define VG_SMEM ((256 * 72 + 64 * 136) * 2)

__global__ __launch_bounds__(512) void v_gemm_mma_kernel(
    const float* __restrict__ x,
    const float* __restrict__ wv, const float* __restrict__ bv)
{
    extern __shared__ __half vsh[];
    __half* Ws = vsh;
    __half* Xs = vsh + VG_XOFF;
    const int b = blockIdx.y, nblk = blockIdx.x, n0 = nblk * 128;
    const int t = threadIdx.x, w = t >> 5, lane = t & 31;
    const int g = lane >> 3, r8 = lane & 7;
    const int cw = w * 16;
    const uint32_t shb = smem_u32(vsh);
    const uint32_t aA = shb + ((cw + (g & 1) * 8 + r8) * 72 + (g >> 1) * 8) * 2;
    const uint32_t aB = shb + VG_XOFF * 2 + ((g & 1) * 8 + r8) * 136 * 2 + (g >> 1) * 16;

    float Acc[16][4];
#pragma unroll
    for (int nb = 0; nb < 16; nb++)
        Acc[nb][0] = Acc[nb][1] = Acc[nb][2] = Acc[nb][3] = 0.f;

    for (int kc = 0; kc < 4; kc++) {
        __syncthreads();
        for (int idx = t; idx < 4096; idx += 512) {
            int row = idx >> 4, col4 = (idx & 15) * 4;
            float4 v = *(const float4*)(wv + row * 256 + kc * 64 + col4);
            uint2 hh;
            __half2 h0 = __floats2half2_rn(v.x, v.y);
            __half2 h1 = __floats2half2_rn(v.z, v.w);
            hh.x = *reinterpret_cast<uint32_t*>(&h0);
            hh.y = *reinterpret_cast<uint32_t*>(&h1);
            *reinterpret_cast<uint2*>(Ws + row * 72 + col4) = hh;
        }
        for (int idx = t; idx < 2048; idx += 512) {
            int row = idx >> 5, col4 = (idx & 31) * 4;
            float4 v = *(const float4*)(x + (size_t)(b * 256 + kc * 64 + row) * 4096 + n0 + col4);
            uint2 hh;
            __half2 h0 = __floats2half2_rn(v.x, v.y);
            __half2 h1 = __floats2half2_rn(v.z, v.w);
            hh.x = *reinterpret_cast<uint32_t*>(&h0);
            hh.y = *reinterpret_cast<uint32_t*>(&h1);
            *reinterpret_cast<uint2*>(Xs + row * 136 + col4) = hh;
        }
        __syncthreads();
#pragma unroll
        for (int s = 0; s < 4; s++) {
            uint32_t a0, a1, a2, a3;
            ldsm_x4(a0, a1, a2, a3, aA + s * 32);
#pragma unroll
            for (int p = 0; p < 8; p++) {
                uint32_t b0, b1, b2, b3;
                ldsm_x4_t(b0, b1, b2, b3, aB + s * (16 * 136 * 2) + p * 32);
                mma16816(Acc[2 * p], a0, a1, a2, a3, b0, b1);
                mma16816(Acc[2 * p + 1], a0, a1, a2, a3, b2, b3);
            }
        }
    }

    const int c0 = cw + (lane >> 2);
    const float bv0 = bv[c0], bv1 = bv[c0 + 8];
#pragma unroll
    for (int nb = 0; nb < 16; nb++) {
        int nl = nb * 8 + (lane & 3) * 2;
        int ntl = nblk * 2 + (nl >> 6);
        int key = nl & 63;
        __half* vb = g_vt + (size_t)(b * 64 + ntl) * 256 * 72;
        __half2 h0 = __floats2half2_rn(Acc[nb][0] + bv0, Acc[nb][1] + bv0);
        __half2 h1 = __floats2half2_rn(Acc[nb][2] + bv1, Acc[nb][3] + bv1);
        *reinterpret_cast<uint32_t*>(vb + (size_t)c0 * 72 + key) =
            *reinterpret_cast<uint32_t*>(&h0);
        *reinterpret_cast<uint32_t*>(vb + (size_t)(c0 + 8) * 72 + key) =
            *reinterpret_cast<uint32_t*>(&h1);
    }
}

// ===========================================================================
// Kernel 4: single-pass online-softmax HMMA flash attention + epilogue.
// (round-12 structure: best measured)  64 queries/CTA, 256 threads / 8 warps,
// 2 CTAs/SM. Warp w: row band a=w&1 (32 rows), quarter kq=w>>1.
// smem(halves): Q[0,1536) K2[1536,4608) V2[4608,41472) P[41472,46080)
// ===========================================================================
#define SM_K(buf) (1536 + (buf) * 1536)
#define SM_V(buf) (4608 + (buf) * 18432)
#define SM_P 41472
#define TOT_HALVES 46080
#define ATTN_SMEM_BYTES (TOT_HALVES * 2 + 512 * 4)

__global__ __launch_bounds__(256, 2) void attn_mma_kernel(
    const float* __restrict__ x, const float* __restrict__ gamma,
    float* __restrict__ out)
{
    extern __shared__ __half sh[];
    __half* Ps = sh + SM_P;
    float* s_pmax = (float*)(sh + TOT_HALVES);   // [4][64]
    float* s_lsum = s_pmax + 256;                // [4][64]

    const int b  = blockIdx.y;
    const int qt = blockIdx.x;
    const int j0 = qt * 64;
    const int t  = threadIdx.x;
    const int w  = t >> 5, lane = t & 31;
    const int gr = lane >> 2, ci = lane & 3;
    const int g  = lane >> 3, r8 = lane & 7;
    const int a  = w & 1;                        // row band (rows 32a..32a+31)
    const int kq = w >> 1;                       // key quarter / channel quarter
    const int rb = a * 32;
    const int barid = 1 + a;
    const float L2E = 1.44269504f;
    const uint32_t shb = smem_u32(sh);

    // LDSM lane addresses
    const uint32_t aQ = shb + ((rb + (g & 1) * 8 + r8) * 24 + (g >> 1) * 8) * 2;
    const uint32_t oK = ((kq * 16 + (g >> 1) * 8 + r8) * 24 + (g & 1) * 8) * 2;
    const uint32_t aP = shb + SM_P * 2 +
        ((rb + (g & 1) * 8 + r8) * 72 + (g >> 1) * 8) * 2;
    const uint32_t oV = ((kq * 64 + (g >> 1) * 8 + r8) * 72 + (g & 1) * 8) * 2;

    // prefetch tile 0 (K: 192 f4, V: 2304 f4)
    {
        const float4* kg = (const float4*)(g_kt + (size_t)(b * 64 + 0) * 1536);
        const float4* vg = (const float4*)(g_vt + (size_t)(b * 64 + 0) * 18432);
        uint32_t kd = shb + SM_K(0) * 2;
        uint32_t vd = shb + SM_V(0) * 2;
        for (int i = t; i < 192; i += 256)  cp_async16(kd + i * 16, kg + i);
        for (int i = t; i < 2304; i += 256) cp_async16(vd + i * 16, vg + i);
        CP_COMMIT();
    }
    // Q tile load (192 float4)
    {
        const float4* qg = (const float4*)(g_qt + (size_t)(b * 64 + qt) * 1536);
        float4* qd = (float4*)sh;
        for (int i = t; i < 192; i += 256) qd[i] = qg[i];
    }
    __syncthreads();

    // hoist loop-invariant Q fragments (32 rows x 16 slots per warp)
    uint32_t qf[2][4];
    ldsm_x4(qf[0][0], qf[0][1], qf[0][2], qf[0][3], aQ);
    ldsm_x4(qf[1][0], qf[1][1], qf[1][2], qf[1][3], aQ + 768);

    float O[2][8][4];
#pragma unroll
    for (int m = 0; m < 2; m++)
#pragma unroll
        for (int nb = 0; nb < 8; nb++)
            O[m][nb][0] = O[m][nb][1] = O[m][nb][2] = O[m][nb][3] = 0.f;
    float mrun[4] = {-1e30f, -1e30f, -1e30f, -1e30f};
    float lrun[4] = {0.f, 0.f, 0.f, 0.f};
    const int r0 = rb + gr;                      // thread's 4 rows: r0, +8, +16, +24

    for (int ntl = 0; ntl < 64; ntl++) {
        CP_WAIT0();
        __syncthreads();     // tile data arrived + both buffers coherent

        if (ntl + 1 < 64) {  // prefetch next tile into the other buffer
            int nn = ntl + 1, bf = nn & 1;
            const float4* kg = (const float4*)(g_kt + (size_t)(b * 64 + nn) * 1536);
            const float4* vg = (const float4*)(g_vt + (size_t)(b * 64 + nn) * 18432);
            uint32_t kd = shb + SM_K(bf) * 2;
            uint32_t vd = shb + SM_V(bf) * 2;
            for (int i = t; i < 192; i += 256)  cp_async16(kd + i * 16, kg + i);
            for (int i = t; i < 2304; i += 256) cp_async16(vd + i * 16, vg + i);
            CP_COMMIT();
        }

        const uint32_t kbyte = shb + SM_K(ntl & 1) * 2;
        const uint32_t vbyte = shb + SM_V(ntl & 1) * 2;

        // ---- QK: 32 rows x 16 keys, single f16 step ----
        float S[4][4];       // [m*2+n][d]
#pragma unroll
        for (int i = 0; i < 4; i++) S[i][0] = S[i][1] = S[i][2] = S[i][3] = 0.f;
        {
            uint32_t b0, b1, b2, b3;
            ldsm_x4(b0, b1, b2, b3, kbyte + oK);
            mma16816(S[0], qf[0][0], qf[0][1], qf[0][2], qf[0][3], b0, b1);
            mma16816(S[1], qf[0][0], qf[0][1], qf[0][2], qf[0][3], b2, b3);
            mma16816(S[2], qf[1][0], qf[1][1], qf[1][2], qf[1][3], b0, b1);
            mma16816(S[3], qf[1][0], qf[1][1], qf[1][2], qf[1][3], b2, b3);
        }

        // partial row max over this warp's 16 keys (4 rows/thread)
        float pm[4];
        pm[0] = fmaxf(fmaxf(S[0][0], S[0][1]), fmaxf(S[1][0], S[1][1]));
        pm[1] = fmaxf(fmaxf(S[0][2], S[0][3]), fmaxf(S[1][2], S[1][3]));
        pm[2] = fmaxf(fmaxf(S[2][0], S[2][1]), fmaxf(S[3][0], S[3][1]));
        pm[3] = fmaxf(fmaxf(S[2][2], S[2][3]), fmaxf(S[3][2], S[3][3]));
#pragma unroll
        for (int j = 0; j < 4; j++) {
            pm[j] = fmaxf(pm[j], __shfl_xor_sync(0xffffffffu, pm[j], 1));
            pm[j] = fmaxf(pm[j], __shfl_xor_sync(0xffffffffu, pm[j], 2));
        }
        if (ci == 0) {
#pragma unroll
            for (int j = 0; j < 4; j++)
                s_pmax[kq * 64 + r0 + j * 8] = pm[j];
        }
        BAR4(barid);

        // ---- combined max, exp -> P (f16), l update, O rescale ----
        float sc[4], mL[4];
#pragma unroll
        for (int j = 0; j < 4; j++) {
            int r = r0 + j * 8;
            float mn = fmaxf(fmaxf(s_pmax[r], s_pmax[64 + r]),
                             fmaxf(s_pmax[128 + r], s_pmax[192 + r]));
            mn = fmaxf(mrun[j], mn);
            sc[j] = exp2f((mrun[j] - mn) * L2E);
            mrun[j] = mn;
            mL[j] = mn * L2E;
        }
        float tl[4] = {0.f, 0.f, 0.f, 0.f};
#pragma unroll
        for (int m = 0; m < 2; m++) {
#pragma unroll
            for (int n = 0; n < 2; n++) {
                int idx = m * 2 + n;
                float y0 = fmaf(S[idx][0], L2E, -mL[2 * m]);
                float y1 = fmaf(S[idx][1], L2E, -mL[2 * m]);
                float y2 = fmaf(S[idx][2], L2E, -mL[2 * m + 1]);
                float y3 = fmaf(S[idx][3], L2E, -mL[2 * m + 1]);
                __half2 h0 = h2exp2(__floats2half2_rn(y0, y1));
                __half2 h1 = h2exp2(__floats2half2_rn(y2, y3));
                *reinterpret_cast<uint32_t*>(
                    Ps + (rb + 16 * m + gr) * 72 + kq * 16 + n * 8 + ci * 2) =
                    *reinterpret_cast<uint32_t*>(&h0);
                *reinterpret_cast<uint32_t*>(
                    Ps + (rb + 16 * m + gr + 8) * 72 + kq * 16 + n * 8 + ci * 2) =
                    *reinterpret_cast<uint32_t*>(&h1);
                tl[2 * m]     += __low2float(h0) + __high2float(h0);
                tl[2 * m + 1] += __low2float(h1) + __high2float(h1);
            }
        }
#pragma unroll
        for (int j = 0; j < 4; j++) lrun[j] = lrun[j] * sc[j] + tl[j];

        bool need = (sc[0] != 1.f) | (sc[1] != 1.f) | (sc[2] != 1.f) | (sc[3] != 1.f);
        if (__any_sync(0xffffffffu, need)) {
#pragma unroll
            for (int m = 0; m < 2; m++)
#pragma unroll
                for (int nb = 0; nb < 8; nb++) {
                    O[m][nb][0] *= sc[2 * m]; O[m][nb][1] *= sc[2 * m];
                    O[m][nb][2] *= sc[2 * m + 1]; O[m][nb][3] *= sc[2 * m + 1];
                }
        }
        BAR4(barid);         // band's full P (all 4 key quarters) visible

        // ---- PV: 32 rows x 64 channels ----
#pragma unroll
        for (int s = 0; s < 4; s++) {
            uint32_t pa0, pa1, pa2, pa3, pb0, pb1, pb2, pb3;
            ldsm_x4(pa0, pa1, pa2, pa3, aP + s * 32);
            ldsm_x4(pb0, pb1, pb2, pb3, aP + 2304 + s * 32);
#pragma unroll
            for (int p = 0; p < 4; p++) {
                uint32_t b0, b1, b2, b3;
                ldsm_x4(b0, b1, b2, b3, vbyte + oV + p * 2304 + s * 32);
                mma16816(O[0][2 * p],     pa0, pa1, pa2, pa3, b0, b1);
                mma16816(O[0][2 * p + 1], pa0, pa1, pa2, pa3, b2, b3);
                mma16816(O[1][2 * p],     pb0, pb1, pb2, pb3, b0, b1);
                mma16816(O[1][2 * p + 1], pb0, pb1, pb2, pb3, b2, b3);
            }
        }
    }

    // combine l across the 4 key-quarter warps of each row band
#pragma unroll
    for (int j = 0; j < 4; j++) {
        lrun[j] += __shfl_xor_sync(0xffffffffu, lrun[j], 1);
        lrun[j] += __shfl_xor_sync(0xffffffffu, lrun[j], 2);
    }
    if (ci == 0) {
#pragma unroll
        for (int j = 0; j < 4; j++)
            s_lsum[kq * 64 + r0 + j * 8] = lrun[j];
    }
    __syncthreads();

    // epilogue: out = gamma*O/l + x
    const float gm = gamma[0];
    float li[4];
#pragma unroll
    for (int j = 0; j < 4; j++) {
        int r = r0 + j * 8;
        li[j] = gm / (s_lsum[r] + s_lsum[64 + r] + s_lsum[128 + r] + s_lsum[192 + r]);
    }
#pragma unroll
    for (int m = 0; m < 2; m++) {
        const int row = j0 + rb + 16 * m + gr;
#pragma unroll
        for (int nb = 0; nb < 8; nb++) {
            int ch = kq * 64 + nb * 8 + ci * 2;
            size_t i0 = ((size_t)(b * 256 + ch)) * 4096 + row;
            out[i0]            = O[m][nb][0] * li[2 * m] + x[i0];
            out[i0 + 4096]     = O[m][nb][1] * li[2 * m] + x[i0 + 4096];
            out[i0 + 8]        = O[m][nb][2] * li[2 * m + 1] + x[i0 + 8];
            out[i0 + 4096 + 8] = O[m][nb][3] * li[2 * m + 1] + x[i0 + 4096 + 8];
        }
    }
}

// ===========================================================================
extern "C" void kernel_launch(void* const* d_in, const int* in_sizes, int n_in,
                              void* d_out, int out_size)
{
    const float* x     = (const float*)d_in[0];
    const float* wq    = (const float*)d_in[1];
    const float* bq    = (const float*)d_in[2];
    const float* wk    = (const float*)d_in[3];
    const float* bk    = (const float*)d_in[4];
    const float* wv    = (const float*)d_in[5];
    const float* bv    = (const float*)d_in[6];
    const float* gamma = (const float*)d_in[7];
    const float* eps_q = (const float*)d_in[8];
    const float* eps_k = (const float*)d_in[9];
    float* out = (float*)d_out;

    qk_prepack_kernel<<<192, 256>>>(wq, wk);

    cudaFuncSetAttribute(qk_conv_mma_kernel,
                         cudaFuncAttributeMaxDynamicSharedMemorySize, QKC_BYTES);
    qk_conv_mma_kernel<<<256, 256, QKC_BYTES>>>(x, bq, bk);

    frn_mish_pack_kernel<<<128, 256>>>(eps_q, eps_k);

    cudaFuncSetAttribute(v_gemm_mma_kernel,
                         cudaFuncAttributeMaxDynamicSharedMemorySize, VG_SMEM);
    v_gemm_mma_kernel<<<dim3(32, 4), 512, VG_SMEM>>>(x, wv, bv);

    cudaFuncSetAttribute(attn_mma_kernel,
                         cudaFuncAttributeMaxDynamicSharedMemorySize,
                         ATTN_SMEM_BYTES);
    attn_mma_kernel<<<dim3(64, 4), 256, ATTN_SMEM_BYTES>>>(x, gamma, out);
}

// round 15
// speedup vs baseline: 1.2142x; 1.0492x over previous
#include <cuda_runtime.h>
#include <cuda_fp16.h>
#include <math.h>
#include <stdint.h>

// ---------------------------------------------------------------------------
// B=4, C=256, C16=16, H=W=64, N=4096. Attention: 64 q/CTA (256 CTAs,
// 2 CTAs/SM), 64-key tiles. All producers stage f16 via cp.async from
// pre-converted images; qk conv + v gemm + attention all on HMMA.
// ---------------------------------------------------------------------------

__device__ __half g_xh[4 * 256 * 4096];          // x in f16 (b,c,n)
__device__ __half g_wvh[4 * 256 * 64];           // wv packed per k-chunk [kc][c][64]
__device__ __half g_apk[8 * 32 * 200];           // packed qk weights [kc][co32][200]
__device__ __half g_qr[4 * 16 * 4096];           // raw conv out q (b,c16,n) f16
__device__ __half g_kr[4 * 16 * 4096];           // raw conv out k
__device__ __half g_qt[4 * 64 * 64 * 24];        // Q tiles [b][qt64][row64][24]
__device__ __half g_kt[4 * 64 * 64 * 24];        // K tiles [b][nt][key64][24]
__device__ __half g_vt[4 * 64 * 256 * 72];       // V tiles [b][nt][ch256][72]

// m16n8k16 f16 MMA, fp32 accum (baseline sm_80 PTX -> HMMA on sm_103)
__device__ __forceinline__ void mma16816(float d[4],
    uint32_t a0, uint32_t a1, uint32_t a2, uint32_t a3,
    uint32_t b0, uint32_t b1)
{
    asm volatile(
        "mma.sync.aligned.m16n8k16.row.col.f32.f16.f16.f32 "
        "{%0,%1,%2,%3}, {%4,%5,%6,%7}, {%8,%9}, {%0,%1,%2,%3};"
        : "+f"(d[0]), "+f"(d[1]), "+f"(d[2]), "+f"(d[3])
        : "r"(a0), "r"(a1), "r"(a2), "r"(a3), "r"(b0), "r"(b1));
}
__device__ __forceinline__ void ldsm_x4(uint32_t& r0, uint32_t& r1,
                                        uint32_t& r2, uint32_t& r3, uint32_t a) {
    asm volatile("ldmatrix.sync.aligned.m8n8.x4.shared.b16 {%0,%1,%2,%3}, [%4];"
                 : "=r"(r0), "=r"(r1), "=r"(r2), "=r"(r3) : "r"(a));
}
__device__ __forceinline__ void ldsm_x4_t(uint32_t& r0, uint32_t& r1,
                                          uint32_t& r2, uint32_t& r3, uint32_t a) {
    asm volatile("ldmatrix.sync.aligned.m8n8.x4.trans.shared.b16 {%0,%1,%2,%3}, [%4];"
                 : "=r"(r0), "=r"(r1), "=r"(r2), "=r"(r3) : "r"(a));
}
__device__ __forceinline__ uint32_t smem_u32(const void* p) {
    uint32_t a;
    asm("{ .reg .u64 t; cvta.to.shared.u64 t, %1; cvt.u32.u64 %0, t; }"
        : "=r"(a) : "l"(p));
    return a;
}
__device__ __forceinline__ void cp_async16(uint32_t sm, const void* g) {
    asm volatile("cp.async.cg.shared.global [%0], [%1], 16;"
                 :: "r"(sm), "l"(g) : "memory");
}
#define CP_COMMIT() asm volatile("cp.async.commit_group;" ::: "memory")
#define CP_WAIT0()  asm volatile("cp.async.wait_group 0;" ::: "memory")
#define BAR4(id) asm volatile("bar.sync %0, 128;" :: "r"(id) : "memory")

// ===========================================================================
// Kernel 0: pack everything. Blocks [0,4096): x->f16; [4096,4352): wv pack;
// [4352,4544): qk weight pack.
// ===========================================================================
__global__ __launch_bounds__(256) void pack_all_kernel(
    const float* __restrict__ x, const float* __restrict__ wq,
    const float* __restrict__ wk, const float* __restrict__ wv)
{
    int bid = blockIdx.x;
    if (bid < 4096) {
        int idx = (bid * 256 + threadIdx.x) * 4;
        float4 v = *(const float4*)(x + idx);
        __half2 h0 = __floats2half2_rn(v.x, v.y);
        __half2 h1 = __floats2half2_rn(v.z, v.w);
        uint2 u;
        u.x = *reinterpret_cast<uint32_t*>(&h0);
        u.y = *reinterpret_cast<uint32_t*>(&h1);
        *reinterpret_cast<uint2*>(g_xh + idx) = u;
    } else if (bid < 4352) {
        int idx = (bid - 4096) * 256 + threadIdx.x;   // 0..65535
        int kc = idx >> 14;
        int rem = idx & 16383;
        int c = rem >> 6, k = rem & 63;
        g_wvh[kc * 16384 + c * 64 + k] =
            __float2half_rn(wv[c * 256 + kc * 64 + k]);
    } else {
        int idx = (bid - 4352) * 256 + threadIdx.x;   // 0..49151
        int kc = idx / 6144;
        int rem = idx % 6144;
        int co = rem / 192;
        int kk = rem % 192;
        int tap = kk >> 5, cc = kk & 31;
        float v = 0.f;
        if (co < 16) {
            if (tap < 3) v = wq[(co * 256 + kc * 32 + cc) * 3 + tap];
        } else {
            if (tap >= 3) v = wk[((co - 16) * 256 + kc * 32 + cc) * 3 + (tap - 3)];
        }
        g_apk[(kc * 32 + co) * 200 + kk] = __float2half_rn(v);
    }
}

// ===========================================================================
// Kernel 1: q = conv1x3, k = conv3x1 via HMMA im2col GEMM.
// Grid 256 = (b*64+h). 256 threads / 8 warps. A double-buffered via cp.async;
// X staged as f16 uint loads (stride-70 image, conflict-free); B built
// tap-per-thread with boundary predication.
// smem halves: A0[0,6400) A1[6400,12800) B[12800,25600) X[25600,32320)
// ===========================================================================
#define QKC_B 12800
#define QKC_X 25600
#define QKC_BYTES ((25600 + 6720) * 2)

__global__ __launch_bounds__(256, 2) void qk_conv_mma_kernel(
    const float* __restrict__ bq, const float* __restrict__ bk)
{
    extern __shared__ __half qs[];
    __half* Bs = qs + QKC_B;
    __half* Xs = qs + QKC_X;

    const int b = blockIdx.x >> 6;
    const int h = blockIdx.x & 63;
    const int t = threadIdx.x;
    const int w8 = t >> 5, lane = t & 31;
    const int gr = lane >> 2, ci4 = lane & 3;
    const int g = lane >> 3, r8 = lane & 7;
    const int m = w8 & 1;          // 0 -> q co rows, 1 -> k co rows
    const int p = w8 >> 1;         // w-16 block 0..3
    const uint32_t shb = smem_u32(qs);
    const uint32_t aAoff =
        ((m * 16 + (g & 1) * 8 + r8) * 200 + (g >> 1) * 8) * 2;
    const uint32_t bB = shb + QKC_B * 2 +
        ((p * 16 + (g >> 1) * 8 + r8) * 200 + (g & 1) * 8) * 2;

    float D0[4] = {0.f, 0.f, 0.f, 0.f};
    float D1[4] = {0.f, 0.f, 0.f, 0.f};

    // prologue: A(0) via cp.async
    {
        const char* asrc = (const char*)g_apk;
        for (int i = t; i < 800; i += 256)
            cp_async16(shb + i * 16, asrc + i * 16);
        CP_COMMIT();
    }

    const uint32_t* xs32 = (const uint32_t*)g_xh;
    for (int kc = 0; kc < 8; kc++) {
        // X(kc) staged with plain f16 uint loads (overlaps A cp.async)
        for (int i = t; i < 3072; i += 256) {
            int rc = i >> 5, k = i & 31;
            int dh = rc >> 5, cc = rc & 31;
            int hh = h + dh - 1;
            uint32_t v = 0;
            if (hh >= 0 && hh < 64)
                v = xs32[((size_t)(b * 256 + kc * 32 + cc)) * 2048 + hh * 32 + k];
            ((uint32_t*)(Xs + rc * 70))[k] = v;
        }
        CP_WAIT0();
        __syncthreads();      // A(kc) + X(kc) visible; B free
        // issue A(kc+1)
        if (kc < 8 - 1) {
            const char* asrc = (const char*)g_apk + (kc + 1) * 12800;
            uint32_t ad = shb + ((kc + 1) & 1) * 12800;
            for (int i = t; i < 800; i += 256)
                cp_async16(ad + i * 16, asrc + i * 16);
        }
        CP_COMMIT();
        // build B[w64][k192]
        if (t < 192) {
            int tap = t >> 5, cc = t & 31;
            __half* dst = Bs + t;
            if (tap >= 3) {
                const __half* src = Xs + ((tap - 3) * 32 + cc) * 70;
#pragma unroll 16
                for (int w = 0; w < 64; w++) dst[w * 200] = src[w];
            } else {
                const __half z = __float2half_rn(0.f);
                const __half* src = Xs + (32 + cc) * 70;
#pragma unroll 16
                for (int w = 0; w < 64; w++) {
                    int sidx = w + tap - 1;
                    __half v = z;
                    if (sidx >= 0 && sidx < 64) v = src[sidx];
                    dst[w * 200] = v;
                }
            }
        }
        __syncthreads();
        // MMA(kc)
        const uint32_t aA = shb + (kc & 1) * 12800 + aAoff;
#pragma unroll
        for (int s = 0; s < 12; s++) {
            uint32_t a0, a1, a2, a3, b0, b1, b2, b3;
            ldsm_x4(a0, a1, a2, a3, aA + s * 32);
            ldsm_x4(b0, b1, b2, b3, bB + s * 32);
            mma16816(D0, a0, a1, a2, a3, b0, b1);
            mma16816(D1, a0, a1, a2, a3, b2, b3);
        }
    }

    // epilogue: + bias, f16 raw outputs
    const float* bias = m ? bk : bq;
    __half* dstb = m ? g_kr : g_qr;
    const float bv0 = bias[gr], bv1 = bias[gr + 8];
    const size_t base0 = ((size_t)(b * 16 + gr)) * 4096 + h * 64 + p * 16 + ci4 * 2;
    const size_t base1 = ((size_t)(b * 16 + gr + 8)) * 4096 + h * 64 + p * 16 + ci4 * 2;
    __half2 h00 = __floats2half2_rn(D0[0] + bv0, D0[1] + bv0);
    __half2 h01 = __floats2half2_rn(D0[2] + bv1, D0[3] + bv1);
    __half2 h10 = __floats2half2_rn(D1[0] + bv0, D1[1] + bv0);
    __half2 h11 = __floats2half2_rn(D1[2] + bv1, D1[3] + bv1);
    *reinterpret_cast<__half2*>(dstb + base0)     = h00;
    *reinterpret_cast<__half2*>(dstb + base1)     = h01;
    *reinterpret_cast<__half2*>(dstb + base0 + 8) = h10;
    *reinterpret_cast<__half2*>(dstb + base1 + 8) = h11;
}

// ===========================================================================
// Kernel 2: FRN + Mish on raw f16 q/k, pack f16 Q/K tile images.
// mish via tanh(softplus(v)) = (u^2-1)/(u^2+1), u = 1+e^v.
// ===========================================================================
__global__ __launch_bounds__(256) void frn_mish_pack_kernel(
    const float* __restrict__ eps_q, const float* __restrict__ eps_k)
{
    __shared__ float red[256];
    __shared__ float sc_s;
    int id = blockIdx.x;                 // 0..127
    int branch = id >> 6;
    int b = (id >> 4) & 3;
    int c = id & 15;
    const __half* p = (branch ? g_kr : g_qr) + (size_t)(b * 16 + c) * 4096;
    float eps = fabsf(branch ? eps_k[c] : eps_q[c]);
    int t = threadIdx.x;

    float s = 0.f;
    for (int i = t; i < 2048; i += 256) {
        float2 f = __half22float2(((const __half2*)p)[i]);
        s += f.x * f.x + f.y * f.y;
    }
    red[t] = s;
    __syncthreads();
    for (int off = 128; off > 0; off >>= 1) {
        if (t < off) red[t] += red[t + off];
        __syncthreads();
    }
    if (t == 0) sc_s = rsqrtf(red[0] / 4096.f + eps);
    __syncthreads();
    float sc = sc_s;
    for (int i = t; i < 4096; i += 256) {
        float v = __half2float(p[i]) * sc;
        float mm;
        if (v > 15.f) {
            mm = v;
        } else {
            float e = __expf(v);
            float u = 1.f + e;
            float u2 = u * u;
            mm = v * __fdividef(u2 - 1.f, u2 + 1.f);
        }
        __half hi = __float2half_rn(mm);
        int row = i & 63, ntl = i >> 6;
        if (!branch)
            g_qt[((size_t)(b * 64 + ntl) * 64 + row) * 24 + c] = hi;
        else
            g_kt[((size_t)(b * 64 + ntl) * 64 + row) * 24 + c] = hi;
    }
}

// ===========================================================================
// Kernel 3: v = wv @ x + bv via HMMA, cp.async double-buffered k-chunks.
// smem halves: Ws0[0,18432) Ws1[18432,36864) Xs0[36864,45568) Xs1[45568,54272)
// ===========================================================================
#define VG_SMEM (54272 * 2)

__global__ __launch_bounds__(512) void v_gemm_mma_kernel(
    const float* __restrict__ bv)
{
    extern __shared__ __half vsh[];
    const int b = blockIdx.y, nblk = blockIdx.x, n0 = nblk * 128;
    const int t = threadIdx.x, w = t >> 5, lane = t & 31;
    const int g = lane >> 3, r8 = lane & 7;
    const int cw = w * 16;
    const uint32_t shb = smem_u32(vsh);
    const uint32_t aAoff = ((cw + (g & 1) * 8 + r8) * 72 + (g >> 1) * 8) * 2;
    const uint32_t aBoff = ((g & 1) * 8 + r8) * 272 + (g >> 1) * 16;

    float Acc[16][4];
#pragma unroll
    for (int nb = 0; nb < 16; nb++)
        Acc[nb][0] = Acc[nb][1] = Acc[nb][2] = Acc[nb][3] = 0.f;

    // stage(kc, buf): Ws (2048 cp) + Xs (1024 cp)
    auto stage = [&](int kc, int buf) {
        uint32_t wd = shb + buf * 36864;
        const __half* wsrc = g_wvh + kc * 16384;
        for (int i = t; i < 2048; i += 512) {
            int row = i >> 3, seg = i & 7;
            cp_async16(wd + row * 144 + seg * 16, wsrc + row * 64 + seg * 8);
        }
        uint32_t xd = shb + 73728 + buf * 17408;
        const __half* xsrc = g_xh + ((size_t)(b * 256 + kc * 64)) * 4096 + n0;
        for (int i = t; i < 1024; i += 512) {
            int row = i >> 4, seg = i & 15;
            cp_async16(xd + row * 272 + seg * 16, xsrc + (size_t)row * 4096 + seg * 8);
        }
        CP_COMMIT();
    };

    stage(0, 0);
    for (int kc = 0; kc < 4; kc++) {
        CP_WAIT0();
        __syncthreads();
        if (kc < 3) stage(kc + 1, (kc + 1) & 1);
        const uint32_t aA = shb + (kc & 1) * 36864 + aAoff;
        const uint32_t aB = shb + 73728 + (kc & 1) * 17408 + aBoff;
#pragma unroll
        for (int s = 0; s < 4; s++) {
            uint32_t a0, a1, a2, a3;
            ldsm_x4(a0, a1, a2, a3, aA + s * 32);
#pragma unroll
            for (int pp = 0; pp < 8; pp++) {
                uint32_t b0, b1, b2, b3;
                ldsm_x4_t(b0, b1, b2, b3, aB + s * 4352 + pp * 32);
                mma16816(Acc[2 * pp], a0, a1, a2, a3, b0, b1);
                mma16816(Acc[2 * pp + 1], a0, a1, a2, a3, b2, b3);
            }
        }
    }

    const int c0 = cw + (lane >> 2);
    const float bv0 = bv[c0], bv1 = bv[c0 + 8];
#pragma unroll
    for (int nb = 0; nb < 16; nb++) {
        int nl = nb * 8 + (lane & 3) * 2;
        int ntl = nblk * 2 + (nl >> 6);
        int key = nl & 63;
        __half* vb = g_vt + (size_t)(b * 64 + ntl) * 256 * 72;
        __half2 h0 = __floats2half2_rn(Acc[nb][0] + bv0, Acc[nb][1] + bv0);
        __half2 h1 = __floats2half2_rn(Acc[nb][2] + bv1, Acc[nb][3] + bv1);
        *reinterpret_cast<uint32_t*>(vb + (size_t)c0 * 72 + key) =
            *reinterpret_cast<uint32_t*>(&h0);
        *reinterpret_cast<uint32_t*>(vb + (size_t)(c0 + 8) * 72 + key) =
            *reinterpret_cast<uint32_t*>(&h1);
    }
}

// ===========================================================================
// Kernel 4: single-pass online-softmax HMMA flash attention + epilogue.
// (round-12/14 structure: best measured) 64 queries/CTA, 256 threads, 2 CTAs/SM.
// smem(halves): Q[0,1536) K2[1536,4608) V2[4608,41472) P[41472,46080)
// ===========================================================================
#define SM_K(buf) (1536 + (buf) * 1536)
#define SM_V(buf) (4608 + (buf) * 18432)
#define SM_P 41472
#define TOT_HALVES 46080
#define ATTN_SMEM_BYTES (TOT_HALVES * 2 + 512 * 4)

__global__ __launch_bounds__(256, 2) void attn_mma_kernel(
    const float* __restrict__ x, const float* __restrict__ gamma,
    float* __restrict__ out)
{
    extern __shared__ __half sh[];
    __half* Ps = sh + SM_P;
    float* s_pmax = (float*)(sh + TOT_HALVES);   // [4][64]
    float* s_lsum = s_pmax + 256;                // [4][64]

    const int b  = blockIdx.y;
    const int qt = blockIdx.x;
    const int j0 = qt * 64;
    const int t  = threadIdx.x;
    const int w  = t >> 5, lane = t & 31;
    const int gr = lane >> 2, ci = lane & 3;
    const int g  = lane >> 3, r8 = lane & 7;
    const int a  = w & 1;
    const int kq = w >> 1;
    const int rb = a * 32;
    const int barid = 1 + a;
    const float L2E = 1.44269504f;
    const uint32_t shb = smem_u32(sh);

    const uint32_t aQ = shb + ((rb + (g & 1) * 8 + r8) * 24 + (g >> 1) * 8) * 2;
    const uint32_t oK = ((kq * 16 + (g >> 1) * 8 + r8) * 24 + (g & 1) * 8) * 2;
    const uint32_t aP = shb + SM_P * 2 +
        ((rb + (g & 1) * 8 + r8) * 72 + (g >> 1) * 8) * 2;
    const uint32_t oV = ((kq * 64 + (g >> 1) * 8 + r8) * 72 + (g & 1) * 8) * 2;

    {
        const float4* kg = (const float4*)(g_kt + (size_t)(b * 64 + 0) * 1536);
        const float4* vg = (const float4*)(g_vt + (size_t)(b * 64 + 0) * 18432);
        uint32_t kd = shb + SM_K(0) * 2;
        uint32_t vd = shb + SM_V(0) * 2;
        for (int i = t; i < 192; i += 256)  cp_async16(kd + i * 16, kg + i);
        for (int i = t; i < 2304; i += 256) cp_async16(vd + i * 16, vg + i);
        CP_COMMIT();
    }
    {
        const float4* qg = (const float4*)(g_qt + (size_t)(b * 64 + qt) * 1536);
        float4* qd = (float4*)sh;
        for (int i = t; i < 192; i += 256) qd[i] = qg[i];
    }
    __syncthreads();

    uint32_t qf[2][4];
    ldsm_x4(qf[0][0], qf[0][1], qf[0][2], qf[0][3], aQ);
    ldsm_x4(qf[1][0], qf[1][1], qf[1][2], qf[1][3], aQ + 768);

    float O[2][8][4];
#pragma unroll
    for (int m = 0; m < 2; m++)
#pragma unroll
        for (int nb = 0; nb < 8; nb++)
            O[m][nb][0] = O[m][nb][1] = O[m][nb][2] = O[m][nb][3] = 0.f;
    float mrun[4] = {-1e30f, -1e30f, -1e30f, -1e30f};
    float lrun[4] = {0.f, 0.f, 0.f, 0.f};
    const int r0 = rb + gr;

    for (int ntl = 0; ntl < 64; ntl++) {
        CP_WAIT0();
        __syncthreads();

        if (ntl + 1 < 64) {
            int nn = ntl + 1, bf = nn & 1;
            const float4* kg = (const float4*)(g_kt + (size_t)(b * 64 + nn) * 1536);
            const float4* vg = (const float4*)(g_vt + (size_t)(b * 64 + nn) * 18432);
            uint32_t kd = shb + SM_K(bf) * 2;
            uint32_t vd = shb + SM_V(bf) * 2;
            for (int i = t; i < 192; i += 256)  cp_async16(kd + i * 16, kg + i);
            for (int i = t; i < 2304; i += 256) cp_async16(vd + i * 16, vg + i);
            CP_COMMIT();
        }

        const uint32_t kbyte = shb + SM_K(ntl & 1) * 2;
        const uint32_t vbyte = shb + SM_V(ntl & 1) * 2;

        float S[4][4];
#pragma unroll
        for (int i = 0; i < 4; i++) S[i][0] = S[i][1] = S[i][2] = S[i][3] = 0.f;
        {
            uint32_t b0, b1, b2, b3;
            ldsm_x4(b0, b1, b2, b3, kbyte + oK);
            mma16816(S[0], qf[0][0], qf[0][1], qf[0][2], qf[0][3], b0, b1);
            mma16816(S[1], qf[0][0], qf[0][1], qf[0][2], qf[0][3], b2, b3);
            mma16816(S[2], qf[1][0], qf[1][1], qf[1][2], qf[1][3], b0, b1);
            mma16816(S[3], qf[1][0], qf[1][1], qf[1][2], qf[1][3], b2, b3);
        }

        float pm[4];
        pm[0] = fmaxf(fmaxf(S[0][0], S[0][1]), fmaxf(S[1][0], S[1][1]));
        pm[1] = fmaxf(fmaxf(S[0][2], S[0][3]), fmaxf(S[1][2], S[1][3]));
        pm[2] = fmaxf(fmaxf(S[2][0], S[2][1]), fmaxf(S[3][0], S[3][1]));
        pm[3] = fmaxf(fmaxf(S[2][2], S[2][3]), fmaxf(S[3][2], S[3][3]));
#pragma unroll
        for (int j = 0; j < 4; j++) {
            pm[j] = fmaxf(pm[j], __shfl_xor_sync(0xffffffffu, pm[j], 1));
            pm[j] = fmaxf(pm[j], __shfl_xor_sync(0xffffffffu, pm[j], 2));
        }
        if (ci == 0) {
#pragma unroll
            for (int j = 0; j < 4; j++)
                s_pmax[kq * 64 + r0 + j * 8] = pm[j];
        }
        BAR4(barid);

        float sc[4], mL[4];
#pragma unroll
        for (int j = 0; j < 4; j++) {
            int r = r0 + j * 8;
            float mn = fmaxf(fmaxf(s_pmax[r], s_pmax[64 + r]),
                             fmaxf(s_pmax[128 + r], s_pmax[192 + r]));
            mn = fmaxf(mrun[j], mn);
            sc[j] = exp2f((mrun[j] - mn) * L2E);
            mrun[j] = mn;
            mL[j] = mn * L2E;
        }
        float tl[4] = {0.f, 0.f, 0.f, 0.f};
#pragma unroll
        for (int m = 0; m < 2; m++) {
#pragma unroll
            for (int n = 0; n < 2; n++) {
                int idx = m * 2 + n;
                float y0 = fmaf(S[idx][0], L2E, -mL[2 * m]);
                float y1 = fmaf(S[idx][1], L2E, -mL[2 * m]);
                float y2 = fmaf(S[idx][2], L2E, -mL[2 * m + 1]);
                float y3 = fmaf(S[idx][3], L2E, -mL[2 * m + 1]);
                __half2 h0 = h2exp2(__floats2half2_rn(y0, y1));
                __half2 h1 = h2exp2(__floats2half2_rn(y2, y3));
                *reinterpret_cast<uint32_t*>(
                    Ps + (rb + 16 * m + gr) * 72 + kq * 16 + n * 8 + ci * 2) =
                    *reinterpret_cast<uint32_t*>(&h0);
                *reinterpret_cast<uint32_t*>(
                    Ps + (rb + 16 * m + gr + 8) * 72 + kq * 16 + n * 8 + ci * 2) =
                    *reinterpret_cast<uint32_t*>(&h1);
                tl[2 * m]     += __low2float(h0) + __high2float(h0);
                tl[2 * m + 1] += __low2float(h1) + __high2float(h1);
            }
        }
#pragma unroll
        for (int j = 0; j < 4; j++) lrun[j] = lrun[j] * sc[j] + tl[j];

        bool need = (sc[0] != 1.f) | (sc[1] != 1.f) | (sc[2] != 1.f) | (sc[3] != 1.f);
        if (__any_sync(0xffffffffu, need)) {
#pragma unroll
            for (int m = 0; m < 2; m++)
#pragma unroll
                for (int nb = 0; nb < 8; nb++) {
                    O[m][nb][0] *= sc[2 * m]; O[m][nb][1] *= sc[2 * m];
                    O[m][nb][2] *= sc[2 * m + 1]; O[m][nb][3] *= sc[2 * m + 1];
                }
        }
        BAR4(barid);

#pragma unroll
        for (int s = 0; s < 4; s++) {
            uint32_t pa0, pa1, pa2, pa3, pb0, pb1, pb2, pb3;
            ldsm_x4(pa0, pa1, pa2, pa3, aP + s * 32);
            ldsm_x4(pb0, pb1, pb2, pb3, aP + 2304 + s * 32);
#pragma unroll
            for (int p = 0; p < 4; p++) {
                uint32_t b0, b1, b2, b3;
                ldsm_x4(b0, b1, b2, b3, vbyte + oV + p * 2304 + s * 32);
                mma16816(O[0][2 * p],     pa0, pa1, pa2, pa3, b0, b1);
                mma16816(O[0][2 * p + 1], pa0, pa1, pa2, pa3, b2, b3);
                mma16816(O[1][2 * p],     pb0, pb1, pb2, pb3, b0, b1);
                mma16816(O[1][2 * p + 1], pb0, pb1, pb2, pb3, b2, b3);
            }
        }
    }

#pragma unroll
    for (int j = 0; j < 4; j++) {
        lrun[j] += __shfl_xor_sync(0xffffffffu, lrun[j], 1);
        lrun[j] += __shfl_xor_sync(0xffffffffu, lrun[j], 2);
    }
    if (ci == 0) {
#pragma unroll
        for (int j = 0; j < 4; j++)
            s_lsum[kq * 64 + r0 + j * 8] = lrun[j];
    }
    __syncthreads();

    const float gm = gamma[0];
    float li[4];
#pragma unroll
    for (int j = 0; j < 4; j++) {
        int r = r0 + j * 8;
        li[j] = gm / (s_lsum[r] + s_lsum[64 + r] + s_lsum[128 + r] + s_lsum[192 + r]);
    }
#pragma unroll
    for (int m = 0; m < 2; m++) {
        const int row = j0 + rb + 16 * m + gr;
#pragma unroll
        for (int nb = 0; nb < 8; nb++) {
            int ch = kq * 64 + nb * 8 + ci * 2;
            size_t i0 = ((size_t)(b * 256 + ch)) * 4096 + row;
            out[i0]            = O[m][nb][0] * li[2 * m] + x[i0];
            out[i0 + 4096]     = O[m][nb][1] * li[2 * m] + x[i0 + 4096];
            out[i0 + 8]        = O[m][nb][2] * li[2 * m + 1] + x[i0 + 8];
            out[i0 + 4096 + 8] = O[m][nb][3] * li[2 * m + 1] + x[i0 + 4096 + 8];
        }
    }
}

// ===========================================================================
extern "C" void kernel_launch(void* const* d_in, const int* in_sizes, int n_in,
                              void* d_out, int out_size)
{
    const float* x     = (const float*)d_in[0];
    const float* wq    = (const float*)d_in[1];
    const float* bq    = (const float*)d_in[2];
    const float* wk    = (const float*)d_in[3];
    const float* bk    = (const float*)d_in[4];
    const float* wv    = (const float*)d_in[5];
    const float* bv    = (const float*)d_in[6];
    const float* gamma = (const float*)d_in[7];
    const float* eps_q = (const float*)d_in[8];
    const float* eps_k = (const float*)d_in[9];
    float* out = (float*)d_out;

    pack_all_kernel<<<4544, 256>>>(x, wq, wk, wv);

    cudaFuncSetAttribute(qk_conv_mma_kernel,
                         cudaFuncAttributeMaxDynamicSharedMemorySize, QKC_BYTES);
    qk_conv_mma_kernel<<<256, 256, QKC_BYTES>>>(bq, bk);

    frn_mish_pack_kernel<<<128, 256>>>(eps_q, eps_k);

    cudaFuncSetAttribute(v_gemm_mma_kernel,
                         cudaFuncAttributeMaxDynamicSharedMemorySize, VG_SMEM);
    v_gemm_mma_kernel<<<dim3(32, 4), 512, VG_SMEM>>>(bv);

    cudaFuncSetAttribute(attn_mma_kernel,
                         cudaFuncAttributeMaxDynamicSharedMemorySize,
                         ATTN_SMEM_BYTES);
    attn_mma_kernel<<<dim3(64, 4), 256, ATTN_SMEM_BYTES>>>(x, gamma, out);
}

// round 16
// speedup vs baseline: 1.2583x; 1.0363x over previous
#include <cuda_runtime.h>
#include <cuda_fp16.h>
#include <math.h>
#include <stdint.h>

// ---------------------------------------------------------------------------
// B=4, C=256, C16=16, H=W=64, N=4096. Attention: 64 q/CTA (256 CTAs,
// 2 CTAs/SM), 64-key tiles. Producers fused into ONE kernel: blocks 0-255
// run the qk im2col HMMA conv, blocks 256-511 run the v HMMA gemm (64-col
// tiles, 256 threads, 2 CTAs/SM). All tiles f16, cp.async staged.
// ---------------------------------------------------------------------------

__device__ __half g_xh[4 * 256 * 4096];          // x in f16 (b,c,n)
__device__ __half g_wvh[4 * 256 * 64];           // wv packed per k-chunk [kc][c][64]
__device__ __half g_apk[8 * 32 * 200];           // packed qk weights [kc][co32][200]
__device__ __half g_qr[4 * 16 * 4096];           // raw conv out q (b,c16,n) f16
__device__ __half g_kr[4 * 16 * 4096];           // raw conv out k
__device__ __half g_qt[4 * 64 * 64 * 24];        // Q tiles [b][qt64][row64][24]
__device__ __half g_kt[4 * 64 * 64 * 24];        // K tiles [b][nt][key64][24]
__device__ __half g_vt[4 * 64 * 256 * 72];       // V tiles [b][nt][ch256][72]

// m16n8k16 f16 MMA, fp32 accum (baseline sm_80 PTX -> HMMA on sm_103)
__device__ __forceinline__ void mma16816(float d[4],
    uint32_t a0, uint32_t a1, uint32_t a2, uint32_t a3,
    uint32_t b0, uint32_t b1)
{
    asm volatile(
        "mma.sync.aligned.m16n8k16.row.col.f32.f16.f16.f32 "
        "{%0,%1,%2,%3}, {%4,%5,%6,%7}, {%8,%9}, {%0,%1,%2,%3};"
        : "+f"(d[0]), "+f"(d[1]), "+f"(d[2]), "+f"(d[3])
        : "r"(a0), "r"(a1), "r"(a2), "r"(a3), "r"(b0), "r"(b1));
}
__device__ __forceinline__ void ldsm_x4(uint32_t& r0, uint32_t& r1,
                                        uint32_t& r2, uint32_t& r3, uint32_t a) {
    asm volatile("ldmatrix.sync.aligned.m8n8.x4.shared.b16 {%0,%1,%2,%3}, [%4];"
                 : "=r"(r0), "=r"(r1), "=r"(r2), "=r"(r3) : "r"(a));
}
__device__ __forceinline__ void ldsm_x4_t(uint32_t& r0, uint32_t& r1,
                                          uint32_t& r2, uint32_t& r3, uint32_t a) {
    asm volatile("ldmatrix.sync.aligned.m8n8.x4.trans.shared.b16 {%0,%1,%2,%3}, [%4];"
                 : "=r"(r0), "=r"(r1), "=r"(r2), "=r"(r3) : "r"(a));
}
__device__ __forceinline__ uint32_t smem_u32(const void* p) {
    uint32_t a;
    asm("{ .reg .u64 t; cvta.to.shared.u64 t, %1; cvt.u32.u64 %0, t; }"
        : "=r"(a) : "l"(p));
    return a;
}
__device__ __forceinline__ void cp_async16(uint32_t sm, const void* g) {
    asm volatile("cp.async.cg.shared.global [%0], [%1], 16;"
                 :: "r"(sm), "l"(g) : "memory");
}
#define CP_COMMIT() asm volatile("cp.async.commit_group;" ::: "memory")
#define CP_WAIT0()  asm volatile("cp.async.wait_group 0;" ::: "memory")
#define BAR4(id) asm volatile("bar.sync %0, 128;" :: "r"(id) : "memory")

// ===========================================================================
// Kernel 0: pack everything. Blocks [0,4096): x->f16; [4096,4352): wv pack;
// [4352,4544): qk weight pack.
// ===========================================================================
__global__ __launch_bounds__(256) void pack_all_kernel(
    const float* __restrict__ x, const float* __restrict__ wq,
    const float* __restrict__ wk, const float* __restrict__ wv)
{
    int bid = blockIdx.x;
    if (bid < 4096) {
        int idx = (bid * 256 + threadIdx.x) * 4;
        float4 v = *(const float4*)(x + idx);
        __half2 h0 = __floats2half2_rn(v.x, v.y);
        __half2 h1 = __floats2half2_rn(v.z, v.w);
        uint2 u;
        u.x = *reinterpret_cast<uint32_t*>(&h0);
        u.y = *reinterpret_cast<uint32_t*>(&h1);
        *reinterpret_cast<uint2*>(g_xh + idx) = u;
    } else if (bid < 4352) {
        int idx = (bid - 4096) * 256 + threadIdx.x;   // 0..65535
        int kc = idx >> 14;
        int rem = idx & 16383;
        int c = rem >> 6, k = rem & 63;
        g_wvh[kc * 16384 + c * 64 + k] =
            __float2half_rn(wv[c * 256 + kc * 64 + k]);
    } else {
        int idx = (bid - 4352) * 256 + threadIdx.x;   // 0..49151
        int kc = idx / 6144;
        int rem = idx % 6144;
        int co = rem / 192;
        int kk = rem % 192;
        int tap = kk >> 5, cc = kk & 31;
        float v = 0.f;
        if (co < 16) {
            if (tap < 3) v = wq[(co * 256 + kc * 32 + cc) * 3 + tap];
        } else {
            if (tap >= 3) v = wk[((co - 16) * 256 + kc * 32 + cc) * 3 + (tap - 3)];
        }
        g_apk[(kc * 32 + co) * 200 + kk] = __float2half_rn(v);
    }
}

// ===========================================================================
// Kernel 1 (FUSED producers), 256 threads, 2 CTAs/SM.
// blocks [0,256): qk conv im2col HMMA (b = bid>>6, h = bid&63)
//   smem halves: A0[0,6400) A1[6400,12800) B[12800,25600) X[25600,32320)
// blocks [256,512): v gemm HMMA, 64-col tiles (vb = bid-256: b=vb>>6, nblk=vb&63)
//   smem halves: W0[0,18432) W1[18432,36864) X0[36864,41472) X1[41472,46080)
// ===========================================================================
#define QKC_B 12800
#define QKC_X 25600
#define FUSED_BYTES (46080 * 2)

__global__ __launch_bounds__(256, 2) void fused_producer_kernel(
    const float* __restrict__ bq, const float* __restrict__ bk,
    const float* __restrict__ bv)
{
    extern __shared__ __half fsh[];
    const int bid = blockIdx.x;
    const int t = threadIdx.x;
    const int lane = t & 31;
    const int g = lane >> 3, r8 = lane & 7;
    const uint32_t shb = smem_u32(fsh);

    if (bid < 256) {
        // ----------------- qk conv branch -----------------
        __half* Bs = fsh + QKC_B;
        __half* Xs = fsh + QKC_X;
        const int b = bid >> 6;
        const int h = bid & 63;
        const int w8 = t >> 5;
        const int gr = lane >> 2, ci4 = lane & 3;
        const int m = w8 & 1;          // 0 -> q co rows, 1 -> k co rows
        const int p = w8 >> 1;         // w-16 block 0..3
        const uint32_t aAoff =
            ((m * 16 + (g & 1) * 8 + r8) * 200 + (g >> 1) * 8) * 2;
        const uint32_t bB = shb + QKC_B * 2 +
            ((p * 16 + (g >> 1) * 8 + r8) * 200 + (g & 1) * 8) * 2;

        float D0[4] = {0.f, 0.f, 0.f, 0.f};
        float D1[4] = {0.f, 0.f, 0.f, 0.f};

        {
            const char* asrc = (const char*)g_apk;
            for (int i = t; i < 800; i += 256)
                cp_async16(shb + i * 16, asrc + i * 16);
            CP_COMMIT();
        }

        const uint32_t* xs32 = (const uint32_t*)g_xh;
        for (int kc = 0; kc < 8; kc++) {
            for (int i = t; i < 3072; i += 256) {
                int rc = i >> 5, k = i & 31;
                int dh = rc >> 5, cc = rc & 31;
                int hh = h + dh - 1;
                uint32_t v = 0;
                if (hh >= 0 && hh < 64)
                    v = xs32[((size_t)(b * 256 + kc * 32 + cc)) * 2048 + hh * 32 + k];
                ((uint32_t*)(Xs + rc * 70))[k] = v;
            }
            CP_WAIT0();
            __syncthreads();
            if (kc < 8 - 1) {
                const char* asrc = (const char*)g_apk + (kc + 1) * 12800;
                uint32_t ad = shb + ((kc + 1) & 1) * 12800;
                for (int i = t; i < 800; i += 256)
                    cp_async16(ad + i * 16, asrc + i * 16);
            }
            CP_COMMIT();
            if (t < 192) {
                int tap = t >> 5, cc = t & 31;
                __half* dst = Bs + t;
                if (tap >= 3) {
                    const __half* src = Xs + ((tap - 3) * 32 + cc) * 70;
#pragma unroll 16
                    for (int w = 0; w < 64; w++) dst[w * 200] = src[w];
                } else {
                    const __half z = __float2half_rn(0.f);
                    const __half* src = Xs + (32 + cc) * 70;
#pragma unroll 16
                    for (int w = 0; w < 64; w++) {
                        int sidx = w + tap - 1;
                        __half v = z;
                        if (sidx >= 0 && sidx < 64) v = src[sidx];
                        dst[w * 200] = v;
                    }
                }
            }
            __syncthreads();
            const uint32_t aA = shb + (kc & 1) * 12800 + aAoff;
#pragma unroll
            for (int s = 0; s < 12; s++) {
                uint32_t a0, a1, a2, a3, b0, b1, b2, b3;
                ldsm_x4(a0, a1, a2, a3, aA + s * 32);
                ldsm_x4(b0, b1, b2, b3, bB + s * 32);
                mma16816(D0, a0, a1, a2, a3, b0, b1);
                mma16816(D1, a0, a1, a2, a3, b2, b3);
            }
        }

        const float* bias = m ? bk : bq;
        __half* dstb = m ? g_kr : g_qr;
        const float bv0 = bias[gr], bv1 = bias[gr + 8];
        const size_t base0 = ((size_t)(b * 16 + gr)) * 4096 + h * 64 + p * 16 + ci4 * 2;
        const size_t base1 = ((size_t)(b * 16 + gr + 8)) * 4096 + h * 64 + p * 16 + ci4 * 2;
        __half2 h00 = __floats2half2_rn(D0[0] + bv0, D0[1] + bv0);
        __half2 h01 = __floats2half2_rn(D0[2] + bv1, D0[3] + bv1);
        __half2 h10 = __floats2half2_rn(D1[0] + bv0, D1[1] + bv0);
        __half2 h11 = __floats2half2_rn(D1[2] + bv1, D1[3] + bv1);
        *reinterpret_cast<__half2*>(dstb + base0)     = h00;
        *reinterpret_cast<__half2*>(dstb + base1)     = h01;
        *reinterpret_cast<__half2*>(dstb + base0 + 8) = h10;
        *reinterpret_cast<__half2*>(dstb + base1 + 8) = h11;
    } else {
        // ----------------- v gemm branch (64-col tiles) -----------------
        const int vb = bid - 256;
        const int b = vb >> 6, nblk = vb & 63, n0 = nblk * 64;
        const int w = t >> 5;                 // 8 warps, 32 ch each
        const int cw = w * 32;
        const uint32_t aAoff = ((cw + (g & 1) * 8 + r8) * 72 + (g >> 1) * 8) * 2;
        const uint32_t aBoff = ((g & 1) * 8 + r8) * 144 + (g >> 1) * 16;

        float Acc[2][8][4];
#pragma unroll
        for (int m = 0; m < 2; m++)
#pragma unroll
            for (int nb = 0; nb < 8; nb++)
                Acc[m][nb][0] = Acc[m][nb][1] = Acc[m][nb][2] = Acc[m][nb][3] = 0.f;

        auto stage = [&](int kc, int buf) {
            uint32_t wd = shb + buf * 36864;
            const __half* wsrc = g_wvh + kc * 16384;
            for (int i = t; i < 2048; i += 256) {
                int row = i >> 3, seg = i & 7;
                cp_async16(wd + row * 144 + seg * 16, wsrc + row * 64 + seg * 8);
            }
            uint32_t xd = shb + 73728 + buf * 9216;
            const __half* xsrc = g_xh + ((size_t)(b * 256 + kc * 64)) * 4096 + n0;
            for (int i = t; i < 512; i += 256) {
                int row = i >> 3, seg = i & 7;
                cp_async16(xd + row * 144 + seg * 16, xsrc + (size_t)row * 4096 + seg * 8);
            }
            CP_COMMIT();
        };

        stage(0, 0);
        for (int kc = 0; kc < 4; kc++) {
            CP_WAIT0();
            __syncthreads();
            if (kc < 3) stage(kc + 1, (kc + 1) & 1);
            const uint32_t aA = shb + (kc & 1) * 36864 + aAoff;
            const uint32_t aB = shb + 73728 + (kc & 1) * 9216 + aBoff;
#pragma unroll
            for (int s = 0; s < 4; s++) {
                uint32_t a00, a01, a02, a03, a10, a11, a12, a13;
                ldsm_x4(a00, a01, a02, a03, aA + s * 32);
                ldsm_x4(a10, a11, a12, a13, aA + 2304 + s * 32);
#pragma unroll
                for (int pp = 0; pp < 4; pp++) {
                    uint32_t b0, b1, b2, b3;
                    ldsm_x4_t(b0, b1, b2, b3, aB + s * 2304 + pp * 32);
                    mma16816(Acc[0][2 * pp],     a00, a01, a02, a03, b0, b1);
                    mma16816(Acc[0][2 * pp + 1], a00, a01, a02, a03, b2, b3);
                    mma16816(Acc[1][2 * pp],     a10, a11, a12, a13, b0, b1);
                    mma16816(Acc[1][2 * pp + 1], a10, a11, a12, a13, b2, b3);
                }
            }
        }

        __half* vbp = g_vt + (size_t)(b * 64 + nblk) * 256 * 72;
#pragma unroll
        for (int m = 0; m < 2; m++) {
            const int c0 = cw + m * 16 + (lane >> 2);
            const float bv0 = bv[c0], bv1 = bv[c0 + 8];
#pragma unroll
            for (int nb = 0; nb < 8; nb++) {
                int key = nb * 8 + (lane & 3) * 2;
                __half2 h0 = __floats2half2_rn(Acc[m][nb][0] + bv0, Acc[m][nb][1] + bv0);
                __half2 h1 = __floats2half2_rn(Acc[m][nb][2] + bv1, Acc[m][nb][3] + bv1);
                *reinterpret_cast<uint32_t*>(vbp + (size_t)c0 * 72 + key) =
                    *reinterpret_cast<uint32_t*>(&h0);
                *reinterpret_cast<uint32_t*>(vbp + (size_t)(c0 + 8) * 72 + key) =
                    *reinterpret_cast<uint32_t*>(&h1);
            }
        }
    }
}

// ===========================================================================
// Kernel 2: FRN + Mish on raw f16 q/k, pack f16 Q/K tile images.
// mish via tanh(softplus(v)) = (u^2-1)/(u^2+1), u = 1+e^v.
// ===========================================================================
__global__ __launch_bounds__(256) void frn_mish_pack_kernel(
    const float* __restrict__ eps_q, const float* __restrict__ eps_k)
{
    __shared__ float red[256];
    __shared__ float sc_s;
    int id = blockIdx.x;                 // 0..127
    int branch = id >> 6;
    int b = (id >> 4) & 3;
    int c = id & 15;
    const __half* p = (branch ? g_kr : g_qr) + (size_t)(b * 16 + c) * 4096;
    float eps = fabsf(branch ? eps_k[c] : eps_q[c]);
    int t = threadIdx.x;

    float s = 0.f;
    for (int i = t; i < 2048; i += 256) {
        float2 f = __half22float2(((const __half2*)p)[i]);
        s += f.x * f.x + f.y * f.y;
    }
    red[t] = s;
    __syncthreads();
    for (int off = 128; off > 0; off >>= 1) {
        if (t < off) red[t] += red[t + off];
        __syncthreads();
    }
    if (t == 0) sc_s = rsqrtf(red[0] / 4096.f + eps);
    __syncthreads();
    float sc = sc_s;
    for (int i = t; i < 4096; i += 256) {
        float v = __half2float(p[i]) * sc;
        float mm;
        if (v > 15.f) {
            mm = v;
        } else {
            float e = __expf(v);
            float u = 1.f + e;
            float u2 = u * u;
            mm = v * __fdividef(u2 - 1.f, u2 + 1.f);
        }
        __half hi = __float2half_rn(mm);
        int row = i & 63, ntl = i >> 6;
        if (!branch)
            g_qt[((size_t)(b * 64 + ntl) * 64 + row) * 24 + c] = hi;
        else
            g_kt[((size_t)(b * 64 + ntl) * 64 + row) * 24 + c] = hi;
    }
}

// ===========================================================================
// Kernel 3: single-pass online-softmax HMMA flash attention + epilogue.
// 64 queries/CTA, 256 threads, 2 CTAs/SM.
// smem(halves): Q[0,1536) K2[1536,4608) V2[4608,41472) P[41472,46080)
// ===========================================================================
#define SM_K(buf) (1536 + (buf) * 1536)
#define SM_V(buf) (4608 + (buf) * 18432)
#define SM_P 41472
#define TOT_HALVES 46080
#define ATTN_SMEM_BYTES (TOT_HALVES * 2 + 512 * 4)

__global__ __launch_bounds__(256, 2) void attn_mma_kernel(
    const float* __restrict__ x, const float* __restrict__ gamma,
    float* __restrict__ out)
{
    extern __shared__ __half sh[];
    __half* Ps = sh + SM_P;
    float* s_pmax = (float*)(sh + TOT_HALVES);   // [4][64]
    float* s_lsum = s_pmax + 256;                // [4][64]

    const int b  = blockIdx.y;
    const int qt = blockIdx.x;
    const int j0 = qt * 64;
    const int t  = threadIdx.x;
    const int w  = t >> 5, lane = t & 31;
    const int gr = lane >> 2, ci = lane & 3;
    const int g  = lane >> 3, r8 = lane & 7;
    const int a  = w & 1;
    const int kq = w >> 1;
    const int rb = a * 32;
    const int barid = 1 + a;
    const float L2E = 1.44269504f;
    const uint32_t shb = smem_u32(sh);

    const uint32_t aQ = shb + ((rb + (g & 1) * 8 + r8) * 24 + (g >> 1) * 8) * 2;
    const uint32_t oK = ((kq * 16 + (g >> 1) * 8 + r8) * 24 + (g & 1) * 8) * 2;
    const uint32_t aP = shb + SM_P * 2 +
        ((rb + (g & 1) * 8 + r8) * 72 + (g >> 1) * 8) * 2;
    const uint32_t oV = ((kq * 64 + (g >> 1) * 8 + r8) * 72 + (g & 1) * 8) * 2;

    {
        const float4* kg = (const float4*)(g_kt + (size_t)(b * 64 + 0) * 1536);
        const float4* vg = (const float4*)(g_vt + (size_t)(b * 64 + 0) * 18432);
        uint32_t kd = shb + SM_K(0) * 2;
        uint32_t vd = shb + SM_V(0) * 2;
        for (int i = t; i < 192; i += 256)  cp_async16(kd + i * 16, kg + i);
        for (int i = t; i < 2304; i += 256) cp_async16(vd + i * 16, vg + i);
        CP_COMMIT();
    }
    {
        const float4* qg = (const float4*)(g_qt + (size_t)(b * 64 + qt) * 1536);
        float4* qd = (float4*)sh;
        for (int i = t; i < 192; i += 256) qd[i] = qg[i];
    }
    __syncthreads();

    uint32_t qf[2][4];
    ldsm_x4(qf[0][0], qf[0][1], qf[0][2], qf[0][3], aQ);
    ldsm_x4(qf[1][0], qf[1][1], qf[1][2], qf[1][3], aQ + 768);

    float O[2][8][4];
#pragma unroll
    for (int m = 0; m < 2; m++)
#pragma unroll
        for (int nb = 0; nb < 8; nb++)
            O[m][nb][0] = O[m][nb][1] = O[m][nb][2] = O[m][nb][3] = 0.f;
    float mrun[4] = {-1e30f, -1e30f, -1e30f, -1e30f};
    float lrun[4] = {0.f, 0.f, 0.f, 0.f};
    const int r0 = rb + gr;

    for (int ntl = 0; ntl < 64; ntl++) {
        CP_WAIT0();
        __syncthreads();

        if (ntl + 1 < 64) {
            int nn = ntl + 1, bf = nn & 1;
            const float4* kg = (const float4*)(g_kt + (size_t)(b * 64 + nn) * 1536);
            const float4* vg = (const float4*)(g_vt + (size_t)(b * 64 + nn) * 18432);
            uint32_t kd = shb + SM_K(bf) * 2;
            uint32_t vd = shb + SM_V(bf) * 2;
            for (int i = t; i < 192; i += 256)  cp_async16(kd + i * 16, kg + i);
            for (int i = t; i < 2304; i += 256) cp_async16(vd + i * 16, vg + i);
            CP_COMMIT();
        }

        const uint32_t kbyte = shb + SM_K(ntl & 1) * 2;
        const uint32_t vbyte = shb + SM_V(ntl & 1) * 2;

        float S[4][4];
#pragma unroll
        for (int i = 0; i < 4; i++) S[i][0] = S[i][1] = S[i][2] = S[i][3] = 0.f;
        {
            uint32_t b0, b1, b2, b3;
            ldsm_x4(b0, b1, b2, b3, kbyte + oK);
            mma16816(S[0], qf[0][0], qf[0][1], qf[0][2], qf[0][3], b0, b1);
            mma16816(S[1], qf[0][0], qf[0][1], qf[0][2], qf[0][3], b2, b3);
            mma16816(S[2], qf[1][0], qf[1][1], qf[1][2], qf[1][3], b0, b1);
            mma16816(S[3], qf[1][0], qf[1][1], qf[1][2], qf[1][3], b2, b3);
        }

        float pm[4];
        pm[0] = fmaxf(fmaxf(S[0][0], S[0][1]), fmaxf(S[1][0], S[1][1]));
        pm[1] = fmaxf(fmaxf(S[0][2], S[0][3]), fmaxf(S[1][2], S[1][3]));
        pm[2] = fmaxf(fmaxf(S[2][0], S[2][1]), fmaxf(S[3][0], S[3][1]));
        pm[3] = fmaxf(fmaxf(S[2][2], S[2][3]), fmaxf(S[3][2], S[3][3]));
#pragma unroll
        for (int j = 0; j < 4; j++) {
            pm[j] = fmaxf(pm[j], __shfl_xor_sync(0xffffffffu, pm[j], 1));
            pm[j] = fmaxf(pm[j], __shfl_xor_sync(0xffffffffu, pm[j], 2));
        }
        if (ci == 0) {
#pragma unroll
            for (int j = 0; j < 4; j++)
                s_pmax[kq * 64 + r0 + j * 8] = pm[j];
        }
        BAR4(barid);

        float sc[4], mL[4];
#pragma unroll
        for (int j = 0; j < 4; j++) {
            int r = r0 + j * 8;
            float mn = fmaxf(fmaxf(s_pmax[r], s_pmax[64 + r]),
                             fmaxf(s_pmax[128 + r], s_pmax[192 + r]));
            mn = fmaxf(mrun[j], mn);
            sc[j] = exp2f((mrun[j] - mn) * L2E);
            mrun[j] = mn;
            mL[j] = mn * L2E;
        }
        float tl[4] = {0.f, 0.f, 0.f, 0.f};
#pragma unroll
        for (int m = 0; m < 2; m++) {
#pragma unroll
            for (int n = 0; n < 2; n++) {
                int idx = m * 2 + n;
                float y0 = fmaf(S[idx][0], L2E, -mL[2 * m]);
                float y1 = fmaf(S[idx][1], L2E, -mL[2 * m]);
                float y2 = fmaf(S[idx][2], L2E, -mL[2 * m + 1]);
                float y3 = fmaf(S[idx][3], L2E, -mL[2 * m + 1]);
                __half2 h0 = h2exp2(__floats2half2_rn(y0, y1));
                __half2 h1 = h2exp2(__floats2half2_rn(y2, y3));
                *reinterpret_cast<uint32_t*>(
                    Ps + (rb + 16 * m + gr) * 72 + kq * 16 + n * 8 + ci * 2) =
                    *reinterpret_cast<uint32_t*>(&h0);
                *reinterpret_cast<uint32_t*>(
                    Ps + (rb + 16 * m + gr + 8) * 72 + kq * 16 + n * 8 + ci * 2) =
                    *reinterpret_cast<uint32_t*>(&h1);
                tl[2 * m]     += __low2float(h0) + __high2float(h0);
                tl[2 * m + 1] += __low2float(h1) + __high2float(h1);
            }
        }
#pragma unroll
        for (int j = 0; j < 4; j++) lrun[j] = lrun[j] * sc[j] + tl[j];

        bool need = (sc[0] != 1.f) | (sc[1] != 1.f) | (sc[2] != 1.f) | (sc[3] != 1.f);
        if (__any_sync(0xffffffffu, need)) {
#pragma unroll
            for (int m = 0; m < 2; m++)
#pragma unroll
                for (int nb = 0; nb < 8; nb++) {
                    O[m][nb][0] *= sc[2 * m]; O[m][nb][1] *= sc[2 * m];
                    O[m][nb][2] *= sc[2 * m + 1]; O[m][nb][3] *= sc[2 * m + 1];
                }
        }
        BAR4(barid);

#pragma unroll
        for (int s = 0; s < 4; s++) {
            uint32_t pa0, pa1, pa2, pa3, pb0, pb1, pb2, pb3;
            ldsm_x4(pa0, pa1, pa2, pa3, aP + s * 32);
            ldsm_x4(pb0, pb1, pb2, pb3, aP + 2304 + s * 32);
#pragma unroll
            for (int p = 0; p < 4; p++) {
                uint32_t b0, b1, b2, b3;
                ldsm_x4(b0, b1, b2, b3, vbyte + oV + p * 2304 + s * 32);
                mma16816(O[0][2 * p],     pa0, pa1, pa2, pa3, b0, b1);
                mma16816(O[0][2 * p + 1], pa0, pa1, pa2, pa3, b2, b3);
                mma16816(O[1][2 * p],     pb0, pb1, pb2, pb3, b0, b1);
                mma16816(O[1][2 * p + 1], pb0, pb1, pb2, pb3, b2, b3);
            }
        }
    }

#pragma unroll
    for (int j = 0; j < 4; j++) {
        lrun[j] += __shfl_xor_sync(0xffffffffu, lrun[j], 1);
        lrun[j] += __shfl_xor_sync(0xffffffffu, lrun[j], 2);
    }
    if (ci == 0) {
#pragma unroll
        for (int j = 0; j < 4; j++)
            s_lsum[kq * 64 + r0 + j * 8] = lrun[j];
    }
    __syncthreads();

    const float gm = gamma[0];
    float li[4];
#pragma unroll
    for (int j = 0; j < 4; j++) {
        int r = r0 + j * 8;
        li[j] = gm / (s_lsum[r] + s_lsum[64 + r] + s_lsum[128 + r] + s_lsum[192 + r]);
    }
#pragma unroll
    for (int m = 0; m < 2; m++) {
        const int row = j0 + rb + 16 * m + gr;
#pragma unroll
        for (int nb = 0; nb < 8; nb++) {
            int ch = kq * 64 + nb * 8 + ci * 2;
            size_t i0 = ((size_t)(b * 256 + ch)) * 4096 + row;
            out[i0]            = O[m][nb][0] * li[2 * m] + x[i0];
            out[i0 + 4096]     = O[m][nb][1] * li[2 * m] + x[i0 + 4096];
            out[i0 + 8]        = O[m][nb][2] * li[2 * m + 1] + x[i0 + 8];
            out[i0 + 4096 + 8] = O[m][nb][3] * li[2 * m + 1] + x[i0 + 4096 + 8];
        }
    }
}

// ===========================================================================
extern "C" void kernel_launch(void* const* d_in, const int* in_sizes, int n_in,
                              void* d_out, int out_size)
{
    const float* x     = (const float*)d_in[0];
    const float* wq    = (const float*)d_in[1];
    const float* bq    = (const float*)d_in[2];
    const float* wk    = (const float*)d_in[3];
    const float* bk    = (const float*)d_in[4];
    const float* wv    = (const float*)d_in[5];
    const float* bv    = (const float*)d_in[6];
    const float* gamma = (const float*)d_in[7];
    const float* eps_q = (const float*)d_in[8];
    const float* eps_k = (const float*)d_in[9];
    float* out = (float*)d_out;

    pack_all_kernel<<<4544, 256>>>(x, wq, wk, wv);

    cudaFuncSetAttribute(fused_producer_kernel,
                         cudaFuncAttributeMaxDynamicSharedMemorySize, FUSED_BYTES);
    fused_producer_kernel<<<512, 256, FUSED_BYTES>>>(bq, bk, bv);

    frn_mish_pack_kernel<<<128, 256>>>(eps_q, eps_k);

    cudaFuncSetAttribute(attn_mma_kernel,
                         cudaFuncAttributeMaxDynamicSharedMemorySize,
                         ATTN_SMEM_BYTES);
    attn_mma_kernel<<<dim3(64, 4), 256, ATTN_SMEM_BYTES>>>(x, gamma, out);
}

// round 17
// speedup vs baseline: 1.3686x; 1.0877x over previous
#include <cuda_runtime.h>
#include <cuda_fp16.h>
#include <math.h>
#include <stdint.h>

// ---------------------------------------------------------------------------
// B=4, C=256, C16=16, H=W=64, N=4096. Attention: 64 q/CTA (256 CTAs,
// 2 CTAs/SM), 64-key tiles. Attention is warp-specialized: warps 0-3 own a
// 16-row x 64-key QK band (in-warp max/sum, no exchange barrier), warps 4-7
// issue cp.async prefetch; all 8 warps do PV. Producers fused (qk conv +
// v gemm) on HMMA, f16 tile images everywhere.
// ---------------------------------------------------------------------------

__device__ __half g_xh[4 * 256 * 4096];          // x in f16 (b,c,n)
__device__ __half g_wvh[4 * 256 * 64];           // wv packed per k-chunk [kc][c][64]
__device__ __half g_apk[8 * 32 * 200];           // packed qk weights [kc][co32][200]
__device__ __half g_qr[4 * 16 * 4096];           // raw conv out q (b,c16,n) f16
__device__ __half g_kr[4 * 16 * 4096];           // raw conv out k
__device__ __half g_qt[4 * 64 * 64 * 24];        // Q tiles [b][qt64][row64][24]
__device__ __half g_kt[4 * 64 * 64 * 24];        // K tiles [b][nt][key64][24]
__device__ __half g_vt[4 * 64 * 256 * 72];       // V tiles [b][nt][ch256][72]

// m16n8k16 f16 MMA, fp32 accum (baseline sm_80 PTX -> HMMA on sm_103)
__device__ __forceinline__ void mma16816(float d[4],
    uint32_t a0, uint32_t a1, uint32_t a2, uint32_t a3,
    uint32_t b0, uint32_t b1)
{
    asm volatile(
        "mma.sync.aligned.m16n8k16.row.col.f32.f16.f16.f32 "
        "{%0,%1,%2,%3}, {%4,%5,%6,%7}, {%8,%9}, {%0,%1,%2,%3};"
        : "+f"(d[0]), "+f"(d[1]), "+f"(d[2]), "+f"(d[3])
        : "r"(a0), "r"(a1), "r"(a2), "r"(a3), "r"(b0), "r"(b1));
}
__device__ __forceinline__ void ldsm_x4(uint32_t& r0, uint32_t& r1,
                                        uint32_t& r2, uint32_t& r3, uint32_t a) {
    asm volatile("ldmatrix.sync.aligned.m8n8.x4.shared.b16 {%0,%1,%2,%3}, [%4];"
                 : "=r"(r0), "=r"(r1), "=r"(r2), "=r"(r3) : "r"(a));
}
__device__ __forceinline__ void ldsm_x4_t(uint32_t& r0, uint32_t& r1,
                                          uint32_t& r2, uint32_t& r3, uint32_t a) {
    asm volatile("ldmatrix.sync.aligned.m8n8.x4.trans.shared.b16 {%0,%1,%2,%3}, [%4];"
                 : "=r"(r0), "=r"(r1), "=r"(r2), "=r"(r3) : "r"(a));
}
__device__ __forceinline__ uint32_t smem_u32(const void* p) {
    uint32_t a;
    asm("{ .reg .u64 t; cvta.to.shared.u64 t, %1; cvt.u32.u64 %0, t; }"
        : "=r"(a) : "l"(p));
    return a;
}
__device__ __forceinline__ void cp_async16(uint32_t sm, const void* g) {
    asm volatile("cp.async.cg.shared.global [%0], [%1], 16;"
                 :: "r"(sm), "l"(g) : "memory");
}
#define CP_COMMIT() asm volatile("cp.async.commit_group;" ::: "memory")
#define CP_WAIT0()  asm volatile("cp.async.wait_group 0;" ::: "memory")

// ===========================================================================
// Kernel 0: pack everything. Blocks [0,4096): x->f16; [4096,4352): wv pack;
// [4352,4544): qk weight pack.
// ===========================================================================
__global__ __launch_bounds__(256) void pack_all_kernel(
    const float* __restrict__ x, const float* __restrict__ wq,
    const float* __restrict__ wk, const float* __restrict__ wv)
{
    int bid = blockIdx.x;
    if (bid < 4096) {
        int idx = (bid * 256 + threadIdx.x) * 4;
        float4 v = *(const float4*)(x + idx);
        __half2 h0 = __floats2half2_rn(v.x, v.y);
        __half2 h1 = __floats2half2_rn(v.z, v.w);
        uint2 u;
        u.x = *reinterpret_cast<uint32_t*>(&h0);
        u.y = *reinterpret_cast<uint32_t*>(&h1);
        *reinterpret_cast<uint2*>(g_xh + idx) = u;
    } else if (bid < 4352) {
        int idx = (bid - 4096) * 256 + threadIdx.x;   // 0..65535
        int kc = idx >> 14;
        int rem = idx & 16383;
        int c = rem >> 6, k = rem & 63;
        g_wvh[kc * 16384 + c * 64 + k] =
            __float2half_rn(wv[c * 256 + kc * 64 + k]);
    } else {
        int idx = (bid - 4352) * 256 + threadIdx.x;   // 0..49151
        int kc = idx / 6144;
        int rem = idx % 6144;
        int co = rem / 192;
        int kk = rem % 192;
        int tap = kk >> 5, cc = kk & 31;
        float v = 0.f;
        if (co < 16) {
            if (tap < 3) v = wq[(co * 256 + kc * 32 + cc) * 3 + tap];
        } else {
            if (tap >= 3) v = wk[((co - 16) * 256 + kc * 32 + cc) * 3 + (tap - 3)];
        }
        g_apk[(kc * 32 + co) * 200 + kk] = __float2half_rn(v);
    }
}

// ===========================================================================
// Kernel 1 (FUSED producers), 256 threads, 2 CTAs/SM.
// blocks [0,256): qk conv im2col HMMA; blocks [256,512): v gemm HMMA.
// ===========================================================================
#define QKC_B 12800
#define QKC_X 25600
#define FUSED_BYTES (46080 * 2)

__global__ __launch_bounds__(256, 2) void fused_producer_kernel(
    const float* __restrict__ bq, const float* __restrict__ bk,
    const float* __restrict__ bv)
{
    extern __shared__ __half fsh[];
    const int bid = blockIdx.x;
    const int t = threadIdx.x;
    const int lane = t & 31;
    const int g = lane >> 3, r8 = lane & 7;
    const uint32_t shb = smem_u32(fsh);

    if (bid < 256) {
        // ----------------- qk conv branch -----------------
        __half* Bs = fsh + QKC_B;
        __half* Xs = fsh + QKC_X;
        const int b = bid >> 6;
        const int h = bid & 63;
        const int w8 = t >> 5;
        const int gr = lane >> 2, ci4 = lane & 3;
        const int m = w8 & 1;
        const int p = w8 >> 1;
        const uint32_t aAoff =
            ((m * 16 + (g & 1) * 8 + r8) * 200 + (g >> 1) * 8) * 2;
        const uint32_t bB = shb + QKC_B * 2 +
            ((p * 16 + (g >> 1) * 8 + r8) * 200 + (g & 1) * 8) * 2;

        float D0[4] = {0.f, 0.f, 0.f, 0.f};
        float D1[4] = {0.f, 0.f, 0.f, 0.f};

        {
            const char* asrc = (const char*)g_apk;
            for (int i = t; i < 800; i += 256)
                cp_async16(shb + i * 16, asrc + i * 16);
            CP_COMMIT();
        }

        const uint32_t* xs32 = (const uint32_t*)g_xh;
        for (int kc = 0; kc < 8; kc++) {
            for (int i = t; i < 3072; i += 256) {
                int rc = i >> 5, k = i & 31;
                int dh = rc >> 5, cc = rc & 31;
                int hh = h + dh - 1;
                uint32_t v = 0;
                if (hh >= 0 && hh < 64)
                    v = xs32[((size_t)(b * 256 + kc * 32 + cc)) * 2048 + hh * 32 + k];
                ((uint32_t*)(Xs + rc * 70))[k] = v;
            }
            CP_WAIT0();
            __syncthreads();
            if (kc < 8 - 1) {
                const char* asrc = (const char*)g_apk + (kc + 1) * 12800;
                uint32_t ad = shb + ((kc + 1) & 1) * 12800;
                for (int i = t; i < 800; i += 256)
                    cp_async16(ad + i * 16, asrc + i * 16);
            }
            CP_COMMIT();
            if (t < 192) {
                int tap = t >> 5, cc = t & 31;
                __half* dst = Bs + t;
                if (tap >= 3) {
                    const __half* src = Xs + ((tap - 3) * 32 + cc) * 70;
#pragma unroll 16
                    for (int w = 0; w < 64; w++) dst[w * 200] = src[w];
                } else {
                    const __half z = __float2half_rn(0.f);
                    const __half* src = Xs + (32 + cc) * 70;
#pragma unroll 16
                    for (int w = 0; w < 64; w++) {
                        int sidx = w + tap - 1;
                        __half v = z;
                        if (sidx >= 0 && sidx < 64) v = src[sidx];
                        dst[w * 200] = v;
                    }
                }
            }
            __syncthreads();
            const uint32_t aA = shb + (kc & 1) * 12800 + aAoff;
#pragma unroll
            for (int s = 0; s < 12; s++) {
                uint32_t a0, a1, a2, a3, b0, b1, b2, b3;
                ldsm_x4(a0, a1, a2, a3, aA + s * 32);
                ldsm_x4(b0, b1, b2, b3, bB + s * 32);
                mma16816(D0, a0, a1, a2, a3, b0, b1);
                mma16816(D1, a0, a1, a2, a3, b2, b3);
            }
        }

        const float* bias = m ? bk : bq;
        __half* dstb = m ? g_kr : g_qr;
        const float bv0 = bias[gr], bv1 = bias[gr + 8];
        const size_t base0 = ((size_t)(b * 16 + gr)) * 4096 + h * 64 + p * 16 + ci4 * 2;
        const size_t base1 = ((size_t)(b * 16 + gr + 8)) * 4096 + h * 64 + p * 16 + ci4 * 2;
        __half2 h00 = __floats2half2_rn(D0[0] + bv0, D0[1] + bv0);
        __half2 h01 = __floats2half2_rn(D0[2] + bv1, D0[3] + bv1);
        __half2 h10 = __floats2half2_rn(D1[0] + bv0, D1[1] + bv0);
        __half2 h11 = __floats2half2_rn(D1[2] + bv1, D1[3] + bv1);
        *reinterpret_cast<__half2*>(dstb + base0)     = h00;
        *reinterpret_cast<__half2*>(dstb + base1)     = h01;
        *reinterpret_cast<__half2*>(dstb + base0 + 8) = h10;
        *reinterpret_cast<__half2*>(dstb + base1 + 8) = h11;
    } else {
        // ----------------- v gemm branch (64-col tiles) -----------------
        const int vb = bid - 256;
        const int b = vb >> 6, nblk = vb & 63, n0 = nblk * 64;
        const int w = t >> 5;
        const int cw = w * 32;
        const uint32_t aAoff = ((cw + (g & 1) * 8 + r8) * 72 + (g >> 1) * 8) * 2;
        const uint32_t aBoff = ((g & 1) * 8 + r8) * 144 + (g >> 1) * 16;

        float Acc[2][8][4];
#pragma unroll
        for (int m = 0; m < 2; m++)
#pragma unroll
            for (int nb = 0; nb < 8; nb++)
                Acc[m][nb][0] = Acc[m][nb][1] = Acc[m][nb][2] = Acc[m][nb][3] = 0.f;

        auto stage = [&](int kc, int buf) {
            uint32_t wd = shb + buf * 36864;
            const __half* wsrc = g_wvh + kc * 16384;
            for (int i = t; i < 2048; i += 256) {
                int row = i >> 3, seg = i & 7;
                cp_async16(wd + row * 144 + seg * 16, wsrc + row * 64 + seg * 8);
            }
            uint32_t xd = shb + 73728 + buf * 9216;
            const __half* xsrc = g_xh + ((size_t)(b * 256 + kc * 64)) * 4096 + n0;
            for (int i = t; i < 512; i += 256) {
                int row = i >> 3, seg = i & 7;
                cp_async16(xd + row * 144 + seg * 16, xsrc + (size_t)row * 4096 + seg * 8);
            }
            CP_COMMIT();
        };

        stage(0, 0);
        for (int kc = 0; kc < 4; kc++) {
            CP_WAIT0();
            __syncthreads();
            if (kc < 3) stage(kc + 1, (kc + 1) & 1);
            const uint32_t aA = shb + (kc & 1) * 36864 + aAoff;
            const uint32_t aB = shb + 73728 + (kc & 1) * 9216 + aBoff;
#pragma unroll
            for (int s = 0; s < 4; s++) {
                uint32_t a00, a01, a02, a03, a10, a11, a12, a13;
                ldsm_x4(a00, a01, a02, a03, aA + s * 32);
                ldsm_x4(a10, a11, a12, a13, aA + 2304 + s * 32);
#pragma unroll
                for (int pp = 0; pp < 4; pp++) {
                    uint32_t b0, b1, b2, b3;
                    ldsm_x4_t(b0, b1, b2, b3, aB + s * 2304 + pp * 32);
                    mma16816(Acc[0][2 * pp],     a00, a01, a02, a03, b0, b1);
                    mma16816(Acc[0][2 * pp + 1], a00, a01, a02, a03, b2, b3);
                    mma16816(Acc[1][2 * pp],     a10, a11, a12, a13, b0, b1);
                    mma16816(Acc[1][2 * pp + 1], a10, a11, a12, a13, b2, b3);
                }
            }
        }

        __half* vbp = g_vt + (size_t)(b * 64 + nblk) * 256 * 72;
#pragma unroll
        for (int m = 0; m < 2; m++) {
            const int c0 = cw + m * 16 + (lane >> 2);
            const float bv0 = bv[c0], bv1 = bv[c0 + 8];
#pragma unroll
            for (int nb = 0; nb < 8; nb++) {
                int key = nb * 8 + (lane & 3) * 2;
                __half2 h0 = __floats2half2_rn(Acc[m][nb][0] + bv0, Acc[m][nb][1] + bv0);
                __half2 h1 = __floats2half2_rn(Acc[m][nb][2] + bv1, Acc[m][nb][3] + bv1);
                *reinterpret_cast<uint32_t*>(vbp + (size_t)c0 * 72 + key) =
                    *reinterpret_cast<uint32_t*>(&h0);
                *reinterpret_cast<uint32_t*>(vbp + (size_t)(c0 + 8) * 72 + key) =
                    *reinterpret_cast<uint32_t*>(&h1);
            }
        }
    }
}

// ===========================================================================
// Kernel 2: FRN + Mish on raw f16 q/k, pack f16 Q/K tile images.
// ===========================================================================
__global__ __launch_bounds__(256) void frn_mish_pack_kernel(
    const float* __restrict__ eps_q, const float* __restrict__ eps_k)
{
    __shared__ float red[256];
    __shared__ float sc_s;
    int id = blockIdx.x;                 // 0..127
    int branch = id >> 6;
    int b = (id >> 4) & 3;
    int c = id & 15;
    const __half* p = (branch ? g_kr : g_qr) + (size_t)(b * 16 + c) * 4096;
    float eps = fabsf(branch ? eps_k[c] : eps_q[c]);
    int t = threadIdx.x;

    float s = 0.f;
    for (int i = t; i < 2048; i += 256) {
        float2 f = __half22float2(((const __half2*)p)[i]);
        s += f.x * f.x + f.y * f.y;
    }
    red[t] = s;
    __syncthreads();
    for (int off = 128; off > 0; off >>= 1) {
        if (t < off) red[t] += red[t + off];
        __syncthreads();
    }
    if (t == 0) sc_s = rsqrtf(red[0] / 4096.f + eps);
    __syncthreads();
    float sc = sc_s;
    for (int i = t; i < 4096; i += 256) {
        float v = __half2float(p[i]) * sc;
        float mm;
        if (v > 15.f) {
            mm = v;
        } else {
            float e = __expf(v);
            float u = 1.f + e;
            float u2 = u * u;
            mm = v * __fdividef(u2 - 1.f, u2 + 1.f);
        }
        __half hi = __float2half_rn(mm);
        int row = i & 63, ntl = i >> 6;
        if (!branch)
            g_qt[((size_t)(b * 64 + ntl) * 64 + row) * 24 + c] = hi;
        else
            g_kt[((size_t)(b * 64 + ntl) * 64 + row) * 24 + c] = hi;
    }
}

// ===========================================================================
// Kernel 3: warp-specialized single-pass flash attention + epilogue.
// 64 queries/CTA, 256 threads, 2 CTAs/SM.
// Warps 0-3: QK band (rows 16w x 64 keys), in-warp max/sum, softmax, P+sc.
// Warps 4-7: cp.async prefetch of next K/V tile.
// All 8 warps: PV (row band a=w&1, channel quarter kq=w>>1).
// Two __syncthreads per tile; no named barriers, no max exchange.
// smem(halves): Q[0,1536) K2[1536,4608) V2[4608,41472) P[41472,46080)
// ===========================================================================
#define SM_K(buf) (1536 + (buf) * 1536)
#define SM_V(buf) (4608 + (buf) * 18432)
#define SM_P 41472
#define TOT_HALVES 46080
#define ATTN_SMEM_BYTES (TOT_HALVES * 2 + 128 * 4)

__global__ __launch_bounds__(256, 2) void attn_mma_kernel(
    const float* __restrict__ x, const float* __restrict__ gamma,
    float* __restrict__ out)
{
    extern __shared__ __half sh[];
    __half* Ps = sh + SM_P;
    float* s_sc = (float*)(sh + TOT_HALVES);     // [64] per-row rescale
    float* s_l  = s_sc + 64;                     // [64] per-row l

    const int b  = blockIdx.y;
    const int qt = blockIdx.x;
    const int j0 = qt * 64;
    const int t  = threadIdx.x;
    const int w  = t >> 5, lane = t & 31;
    const int gr = lane >> 2, ci = lane & 3;
    const int g  = lane >> 3, r8 = lane & 7;
    const int a  = w & 1;                        // PV row band
    const int kq = w >> 1;                       // PV channel quarter
    const int rb = a * 32;
    const float L2E = 1.44269504f;
    const uint32_t shb = smem_u32(sh);

    // QK-warp addresses (valid for w<4): rows 16w..16w+15
    const uint32_t aQ = shb + ((w * 16 + (g & 1) * 8 + r8) * 24 + (g >> 1) * 8) * 2;
    const uint32_t oK = (((g >> 1) * 8 + r8) * 24 + (g & 1) * 8) * 2;  // +kt*768
    // PV addresses
    const uint32_t aP = shb + SM_P * 2 +
        ((rb + (g & 1) * 8 + r8) * 72 + (g >> 1) * 8) * 2;
    const uint32_t oV = ((kq * 64 + (g >> 1) * 8 + r8) * 72 + (g & 1) * 8) * 2;

    const float4* kgb = (const float4*)(g_kt + (size_t)(b * 64) * 1536);
    const float4* vgb = (const float4*)(g_vt + (size_t)(b * 64) * 18432);

    // prologue: warps 4-7 prefetch tile 0; all load Q
    if (w >= 4) {
        int tt = t - 128;
        uint32_t kd = shb + SM_K(0) * 2;
        uint32_t vd = shb + SM_V(0) * 2;
        for (int i = tt; i < 192; i += 128)  cp_async16(kd + i * 16, kgb + i);
        for (int i = tt; i < 2304; i += 128) cp_async16(vd + i * 16, vgb + i);
        CP_COMMIT();
    }
    {
        const float4* qg = (const float4*)(g_qt + (size_t)(b * 64 + qt) * 1536);
        float4* qd = (float4*)sh;
        if (t < 192) qd[t] = qg[t];
    }
    __syncthreads();

    // QK warps: hoisted Q fragment (16 rows x 16 slots)
    uint32_t qf0 = 0, qf1 = 0, qf2 = 0, qf3 = 0;
    if (w < 4) ldsm_x4(qf0, qf1, qf2, qf3, aQ);

    float O[2][8][4];
#pragma unroll
    for (int m = 0; m < 2; m++)
#pragma unroll
        for (int nb = 0; nb < 8; nb++)
            O[m][nb][0] = O[m][nb][1] = O[m][nb][2] = O[m][nb][3] = 0.f;
    float mrun0 = -1e30f, mrun1 = -1e30f;
    float lrun0 = 0.f, lrun1 = 0.f;
    const int r0 = rb + gr;
    const __half2 l2e2 = __float2half2_rn(L2E);

    for (int ntl = 0; ntl < 64; ntl++) {
        if (w >= 4) CP_WAIT0();
        __syncthreads();     // sync#1: tile data ready; prev P/sc consumed

        const uint32_t kbyte = shb + SM_K(ntl & 1) * 2;
        const uint32_t vbyte = shb + SM_V(ntl & 1) * 2;

        if (w < 4) {
            // ---- QK: 16 rows x 64 keys, packed-f16 S ----
            uint32_t shA[8], shB[8];
#pragma unroll
            for (int kt = 0; kt < 4; kt++) {
                uint32_t b0, b1, b2, b3;
                ldsm_x4(b0, b1, b2, b3, kbyte + oK + kt * 768);
                float S0[4] = {0.f, 0.f, 0.f, 0.f};
                float S1[4] = {0.f, 0.f, 0.f, 0.f};
                mma16816(S0, qf0, qf1, qf2, qf3, b0, b1);
                mma16816(S1, qf0, qf1, qf2, qf3, b2, b3);
                __half2 ha0 = __floats2half2_rn(S0[0], S0[1]);
                __half2 hb0 = __floats2half2_rn(S0[2], S0[3]);
                __half2 ha1 = __floats2half2_rn(S1[0], S1[1]);
                __half2 hb1 = __floats2half2_rn(S1[2], S1[3]);
                shA[2 * kt]     = *reinterpret_cast<uint32_t*>(&ha0);
                shB[2 * kt]     = *reinterpret_cast<uint32_t*>(&hb0);
                shA[2 * kt + 1] = *reinterpret_cast<uint32_t*>(&ha1);
                shB[2 * kt + 1] = *reinterpret_cast<uint32_t*>(&hb1);
            }
            // in-warp row max (rows gr, gr+8)
            __half2 mA = *reinterpret_cast<__half2*>(&shA[0]);
            __half2 mB = *reinterpret_cast<__half2*>(&shB[0]);
#pragma unroll
            for (int nb = 1; nb < 8; nb++) {
                mA = __hmax2(mA, *reinterpret_cast<__half2*>(&shA[nb]));
                mB = __hmax2(mB, *reinterpret_cast<__half2*>(&shB[nb]));
            }
            float m0 = fmaxf(__low2float(mA), __high2float(mA));
            float m1 = fmaxf(__low2float(mB), __high2float(mB));
            m0 = fmaxf(m0, __shfl_xor_sync(0xffffffffu, m0, 1));
            m0 = fmaxf(m0, __shfl_xor_sync(0xffffffffu, m0, 2));
            m1 = fmaxf(m1, __shfl_xor_sync(0xffffffffu, m1, 1));
            m1 = fmaxf(m1, __shfl_xor_sync(0xffffffffu, m1, 2));
            float mn0 = fmaxf(mrun0, m0);
            float mn1 = fmaxf(mrun1, m1);
            float sc0 = exp2f((mrun0 - mn0) * L2E);
            float sc1 = exp2f((mrun1 - mn1) * L2E);
            mrun0 = mn0; mrun1 = mn1;
            __half2 nmL0 = __float2half2_rn(-mn0 * L2E);
            __half2 nmL1 = __float2half2_rn(-mn1 * L2E);
            // exp -> P, l accumulation (f32)
            float tl0 = 0.f, tl1 = 0.f;
            const int row0 = w * 16 + gr;
#pragma unroll
            for (int nb = 0; nb < 8; nb++) {
                __half2 sA = *reinterpret_cast<__half2*>(&shA[nb]);
                __half2 sB = *reinterpret_cast<__half2*>(&shB[nb]);
                __half2 p0 = h2exp2(__hfma2(sA, l2e2, nmL0));
                __half2 p1 = h2exp2(__hfma2(sB, l2e2, nmL1));
                *reinterpret_cast<uint32_t*>(Ps + row0 * 72 + nb * 8 + ci * 2) =
                    *reinterpret_cast<uint32_t*>(&p0);
                *reinterpret_cast<uint32_t*>(Ps + (row0 + 8) * 72 + nb * 8 + ci * 2) =
                    *reinterpret_cast<uint32_t*>(&p1);
                float2 f0 = __half22float2(p0);
                float2 f1 = __half22float2(p1);
                tl0 += f0.x + f0.y;
                tl1 += f1.x + f1.y;
            }
            tl0 += __shfl_xor_sync(0xffffffffu, tl0, 1);
            tl0 += __shfl_xor_sync(0xffffffffu, tl0, 2);
            tl1 += __shfl_xor_sync(0xffffffffu, tl1, 1);
            tl1 += __shfl_xor_sync(0xffffffffu, tl1, 2);
            lrun0 = lrun0 * sc0 + tl0;
            lrun1 = lrun1 * sc1 + tl1;
            if (ci == 0) {
                s_sc[row0] = sc0;
                s_sc[row0 + 8] = sc1;
            }
        } else {
            // ---- prefetch next tile into the other buffer ----
            int nn = ntl + 1;
            if (nn < 64) {
                int bf = nn & 1;
                int tt = t - 128;
                uint32_t kd = shb + SM_K(bf) * 2;
                uint32_t vd = shb + SM_V(bf) * 2;
                const float4* kg = kgb + nn * 192;
                const float4* vg = vgb + (size_t)nn * 2304;
                for (int i = tt; i < 192; i += 128)  cp_async16(kd + i * 16, kg + i);
                for (int i = tt; i < 2304; i += 128) cp_async16(vd + i * 16, vg + i);
                CP_COMMIT();
            }
        }
        __syncthreads();     // sync#2: P + sc ready

        // rescale O (skip when no row updated)
        float sc[4];
#pragma unroll
        for (int j = 0; j < 4; j++) sc[j] = s_sc[r0 + j * 8];
        bool need = (sc[0] != 1.f) | (sc[1] != 1.f) | (sc[2] != 1.f) | (sc[3] != 1.f);
        if (__any_sync(0xffffffffu, need)) {
#pragma unroll
            for (int m = 0; m < 2; m++)
#pragma unroll
                for (int nb = 0; nb < 8; nb++) {
                    O[m][nb][0] *= sc[2 * m]; O[m][nb][1] *= sc[2 * m];
                    O[m][nb][2] *= sc[2 * m + 1]; O[m][nb][3] *= sc[2 * m + 1];
                }
        }

        // ---- PV: 32 rows x 64 channels ----
#pragma unroll
        for (int s = 0; s < 4; s++) {
            uint32_t pa0, pa1, pa2, pa3, pb0, pb1, pb2, pb3;
            ldsm_x4(pa0, pa1, pa2, pa3, aP + s * 32);
            ldsm_x4(pb0, pb1, pb2, pb3, aP + 2304 + s * 32);
#pragma unroll
            for (int p = 0; p < 4; p++) {
                uint32_t b0, b1, b2, b3;
                ldsm_x4(b0, b1, b2, b3, vbyte + oV + p * 2304 + s * 32);
                mma16816(O[0][2 * p],     pa0, pa1, pa2, pa3, b0, b1);
                mma16816(O[0][2 * p + 1], pa0, pa1, pa2, pa3, b2, b3);
                mma16816(O[1][2 * p],     pb0, pb1, pb2, pb3, b0, b1);
                mma16816(O[1][2 * p + 1], pb0, pb1, pb2, pb3, b2, b3);
            }
        }
    }

    // epilogue: QK warps own each row's complete l
    if (w < 4 && ci == 0) {
        s_l[w * 16 + gr] = lrun0;
        s_l[w * 16 + gr + 8] = lrun1;
    }
    __syncthreads();

    const float gm = gamma[0];
    float li[4];
#pragma unroll
    for (int j = 0; j < 4; j++) li[j] = gm / s_l[r0 + j * 8];
#pragma unroll
    for (int m = 0; m < 2; m++) {
        const int row = j0 + rb + 16 * m + gr;
#pragma unroll
        for (int nb = 0; nb < 8; nb++) {
            int ch = kq * 64 + nb * 8 + ci * 2;
            size_t i0 = ((size_t)(b * 256 + ch)) * 4096 + row;
            out[i0]            = O[m][nb][0] * li[2 * m] + x[i0];
            out[i0 + 4096]     = O[m][nb][1] * li[2 * m] + x[i0 + 4096];
            out[i0 + 8]        = O[m][nb][2] * li[2 * m + 1] + x[i0 + 8];
            out[i0 + 4096 + 8] = O[m][nb][3] * li[2 * m + 1] + x[i0 + 4096 + 8];
        }
    }
}

// ===========================================================================
extern "C" void kernel_launch(void* const* d_in, const int* in_sizes, int n_in,
                              void* d_out, int out_size)
{
    const float* x     = (const float*)d_in[0];
    const float* wq    = (const float*)d_in[1];
    const float* bq    = (const float*)d_in[2];
    const float* wk    = (const float*)d_in[3];
    const float* bk    = (const float*)d_in[4];
    const float* wv    = (const float*)d_in[5];
    const float* bv    = (const float*)d_in[6];
    const float* gamma = (const float*)d_in[7];
    const float* eps_q = (const float*)d_in[8];
    const float* eps_k = (const float*)d_in[9];
    float* out = (float*)d_out;

    pack_all_kernel<<<4544, 256>>>(x, wq, wk, wv);

    cudaFuncSetAttribute(fused_producer_kernel,
                         cudaFuncAttributeMaxDynamicSharedMemorySize, FUSED_BYTES);
    fused_producer_kernel<<<512, 256, FUSED_BYTES>>>(bq, bk, bv);

    frn_mish_pack_kernel<<<128, 256>>>(eps_q, eps_k);

    cudaFuncSetAttribute(attn_mma_kernel,
                         cudaFuncAttributeMaxDynamicSharedMemorySize,
                         ATTN_SMEM_BYTES);
    attn_mma_kernel<<<dim3(64, 4), 256, ATTN_SMEM_BYTES>>>(x, gamma, out);
}